// round 1
// baseline (speedup 1.0000x reference)
#include <cuda_runtime.h>
#include <cuda_bf16.h>
#include <math.h>

#define Bb_ 4
#define S_ 1024
#define D_ 1024
#define H_ 16
#define HD_ 64
#define R_ 128
#define NREL 257
#define BS_ (Bb_*S_)   // 4096
#define EPSLN 1e-5f

// -------- device scratch (allocation-free rule: __device__ globals) --------
__device__ float g_h [BS_*D_];                 // LN output (reused for LN2)
__device__ float g_q [BS_*D_];
__device__ float g_k [BS_*D_];
__device__ float g_v [BS_*D_];
__device__ float g_relT[HD_*NREL];             // rel_embed transposed [d][j]
__device__ float g_p [ (size_t)BS_*H_*NREL ];  // rel projection [bs][h][j]
__device__ float g_sc[ (size_t)Bb_*H_*S_*S_ ]; // scores 256MB
__device__ float g_o [BS_*D_];                 // attention output (pre-proj)
__device__ float g_x2[BS_*D_];                 // after first residual
__device__ float g_ff[(size_t)BS_*4*D_];       // FFN intermediate

// ---------------- small helpers ----------------
__device__ __forceinline__ float warp_sum(float v){
  #pragma unroll
  for (int o=16;o>0;o>>=1) v += __shfl_xor_sync(0xffffffffu, v, o);
  return v;
}
__device__ __forceinline__ float warp_max(float v){
  #pragma unroll
  for (int o=16;o>0;o>>=1) v = fmaxf(v, __shfl_xor_sync(0xffffffffu, v, o));
  return v;
}

// ---------------- LayerNorm: one block per row (1024 elems, 256 thr) ----------------
__global__ void __launch_bounds__(256) ln_kernel(const float* __restrict__ x,
                                                 const float* __restrict__ g,
                                                 const float* __restrict__ bta,
                                                 float* __restrict__ y)
{
  int row = blockIdx.x;
  int tid = threadIdx.x;
  const float* xr = x + (size_t)row*D_;
  float4 v = *(const float4*)(xr + tid*4);
  float s  = v.x+v.y+v.z+v.w;
  float ss = v.x*v.x+v.y*v.y+v.z*v.z+v.w*v.w;
  s = warp_sum(s); ss = warp_sum(ss);
  __shared__ float sh[16];
  __shared__ float sh_mu, sh_rs;
  int w = tid>>5, lane = tid&31;
  if (lane==0){ sh[w]=s; sh[8+w]=ss; }
  __syncthreads();
  if (tid==0){
    float S=0.f, SS=0.f;
    #pragma unroll
    for (int i=0;i<8;i++){ S+=sh[i]; SS+=sh[8+i]; }
    float mu  = S*(1.f/(float)D_);
    float var = SS*(1.f/(float)D_) - mu*mu;
    sh_mu = mu; sh_rs = rsqrtf(var + EPSLN);
  }
  __syncthreads();
  float mu = sh_mu, rs = sh_rs;
  float4 gv = *(const float4*)(g   + tid*4);
  float4 bv = *(const float4*)(bta + tid*4);
  float4 o;
  o.x = (v.x-mu)*rs*gv.x + bv.x;
  o.y = (v.y-mu)*rs*gv.y + bv.y;
  o.z = (v.z-mu)*rs*gv.z + bv.z;
  o.w = (v.w-mu)*rs*gv.w + bv.w;
  *(float4*)(y + (size_t)row*D_ + tid*4) = o;
}

// ---------------- generic SGEMM NN 128x128x8, 256 threads, 8x8/thr ----------------
#define EPI_BIAS        0
#define EPI_BIAS_RESID  1
#define EPI_BIAS_GELU   2

template<int EPI>
__global__ void __launch_bounds__(256) sgemm_nn(const float* __restrict__ A,
                                                const float* __restrict__ Bm,
                                                const float* __restrict__ bias,
                                                const float* __restrict__ resid,
                                                float* __restrict__ C,
                                                int M, int N, int K)
{
  __shared__ float As[8][128];
  __shared__ float Bs[8][128];
  const int tid = threadIdx.x;
  const int tx = tid & 15, ty = tid >> 4;
  const int m0 = blockIdx.y*128, n0 = blockIdx.x*128;
  const float* Ab = A + (size_t)m0*K;
  const float* Bp = Bm + n0;
  const int arow = tid >> 1;
  const int acol = (tid & 1)*4;
  const int brow = tid >> 5;       // 0..7
  const int bcol = (tid & 31)*4;   // 0..124
  float acc[8][8];
  #pragma unroll
  for (int i=0;i<8;i++)
    #pragma unroll
    for (int j=0;j<8;j++) acc[i][j]=0.f;

  for (int k0=0;k0<K;k0+=8){
    float4 av = *(const float4*)(Ab + (size_t)arow*K + k0 + acol);
    As[acol+0][arow]=av.x; As[acol+1][arow]=av.y;
    As[acol+2][arow]=av.z; As[acol+3][arow]=av.w;
    *(float4*)&Bs[brow][bcol] = *(const float4*)(Bp + (size_t)(k0+brow)*N + bcol);
    __syncthreads();
    #pragma unroll
    for (int k=0;k<8;k++){
      float a[8], bb[8];
      *(float4*)&a[0]  = *(const float4*)&As[k][ty*4];
      *(float4*)&a[4]  = *(const float4*)&As[k][64+ty*4];
      *(float4*)&bb[0] = *(const float4*)&Bs[k][tx*4];
      *(float4*)&bb[4] = *(const float4*)&Bs[k][64+tx*4];
      #pragma unroll
      for (int i=0;i<8;i++)
        #pragma unroll
        for (int j=0;j<8;j++) acc[i][j] = fmaf(a[i], bb[j], acc[i][j]);
    }
    __syncthreads();
  }

  #pragma unroll
  for (int i=0;i<8;i++){
    int r = m0 + ((i<4)? ty*4+i : 64+ty*4+(i-4));
    #pragma unroll
    for (int j=0;j<8;j++){
      int c = n0 + ((j<4)? tx*4+j : 64+tx*4+(j-4));
      float v = acc[i][j] + bias[c];
      if (EPI==EPI_BIAS_RESID) v += resid[(size_t)r*N + c];
      if (EPI==EPI_BIAS_GELU)  v = 0.5f*v*(1.0f + erff(v*0.70710678118654752f));
      C[(size_t)r*N + c] = v;
    }
  }
}

// ---------------- rel_embed transpose: [257,64] -> [64,257] ----------------
__global__ void rel_transpose(const float* __restrict__ rel, float* __restrict__ relT){
  int i = blockIdx.x*256 + threadIdx.x;
  if (i < NREL*HD_){
    int j = i / HD_, d = i % HD_;
    relT[d*NREL + j] = rel[i];
  }
}

// ---------------- rel projection: P[bs][h][j] = sum_d Q[bs][h*64+d]*rel[j][d] ----------------
__global__ void __launch_bounds__(256) rel_proj(const float* __restrict__ Q,
                                                const float* __restrict__ relT,
                                                float* __restrict__ P)
{
  int bs = blockIdx.x;                 // 0..4095
  __shared__ float sq[D_];
  int tid = threadIdx.x;
  *(float4*)&sq[tid*4] = *(const float4*)(Q + (size_t)bs*D_ + tid*4);
  __syncthreads();

  int hg = tid >> 6;   // 0..3
  int jt = tid & 63;   // 0..63
  float acc[4][5];
  #pragma unroll
  for (int a=0;a<4;a++)
    #pragma unroll
    for (int g=0;g<5;g++) acc[a][g]=0.f;

  for (int d=0; d<HD_; d++){
    const float* rrow = relT + d*NREL;
    float rv[5];
    #pragma unroll
    for (int g=0; g<4; g++) rv[g] = __ldg(rrow + jt + 64*g);
    rv[4] = (jt==0) ? __ldg(rrow + 256) : 0.f;
    #pragma unroll
    for (int hh=0; hh<4; hh++){
      float qv = sq[(hg + 4*hh)*HD_ + d];
      #pragma unroll
      for (int g=0; g<5; g++) acc[hh][g] = fmaf(qv, rv[g], acc[hh][g]);
    }
  }
  #pragma unroll
  for (int hh=0; hh<4; hh++){
    int h = hg + 4*hh;
    float* prow = P + ((size_t)bs*H_ + h)*NREL;
    #pragma unroll
    for (int g=0; g<4; g++) prow[jt + 64*g] = acc[hh][g];
    if (jt==0) prow[256] = acc[hh][4];
  }
}

// ---------------- attention scores: Sc[bh][q][k] = (Q·K^T + Pgather)*scale ----------------
// grid (ktile=8, qtile=8, bh=64), 128x128 tile, K=64 in 4 steps of 16
__global__ void __launch_bounds__(256) attn_scores(const float* __restrict__ Q,
                                                   const float* __restrict__ Kt,
                                                   const float* __restrict__ P,
                                                   float* __restrict__ Sc)
{
  __shared__ float Qs[16][128];
  __shared__ float Ks[16][128];
  int bh = blockIdx.z; int b = bh >> 4, h = bh & 15;
  int q0 = blockIdx.y*128, k0 = blockIdx.x*128;
  int tid = threadIdx.x, tx = tid&15, ty = tid>>4;
  const size_t base = (size_t)b*S_*D_ + h*HD_;
  int lrow = tid>>1;
  int lcol = (tid&1)*8;
  float acc[8][8];
  #pragma unroll
  for (int i=0;i<8;i++)
    #pragma unroll
    for (int j=0;j<8;j++) acc[i][j]=0.f;

  for (int d0=0; d0<HD_; d0+=16){
    const float* qp = Q + base + (size_t)(q0+lrow)*D_ + d0 + lcol;
    float4 v0 = *(const float4*)qp, v1 = *(const float4*)(qp+4);
    Qs[lcol+0][lrow]=v0.x; Qs[lcol+1][lrow]=v0.y; Qs[lcol+2][lrow]=v0.z; Qs[lcol+3][lrow]=v0.w;
    Qs[lcol+4][lrow]=v1.x; Qs[lcol+5][lrow]=v1.y; Qs[lcol+6][lrow]=v1.z; Qs[lcol+7][lrow]=v1.w;
    const float* kp = Kt + base + (size_t)(k0+lrow)*D_ + d0 + lcol;
    float4 w0 = *(const float4*)kp, w1 = *(const float4*)(kp+4);
    Ks[lcol+0][lrow]=w0.x; Ks[lcol+1][lrow]=w0.y; Ks[lcol+2][lrow]=w0.z; Ks[lcol+3][lrow]=w0.w;
    Ks[lcol+4][lrow]=w1.x; Ks[lcol+5][lrow]=w1.y; Ks[lcol+6][lrow]=w1.z; Ks[lcol+7][lrow]=w1.w;
    __syncthreads();
    #pragma unroll
    for (int k=0;k<16;k++){
      float a[8], bb[8];
      *(float4*)&a[0]  = *(const float4*)&Qs[k][ty*4];
      *(float4*)&a[4]  = *(const float4*)&Qs[k][64+ty*4];
      *(float4*)&bb[0] = *(const float4*)&Ks[k][tx*4];
      *(float4*)&bb[4] = *(const float4*)&Ks[k][64+tx*4];
      #pragma unroll
      for (int i=0;i<8;i++)
        #pragma unroll
        for (int j=0;j<8;j++) acc[i][j] = fmaf(a[i], bb[j], acc[i][j]);
    }
    __syncthreads();
  }

  const float scale = 0.125f;  // 1/sqrt(64)
  #pragma unroll
  for (int i=0;i<8;i++){
    int q = q0 + ((i<4)? ty*4+i : 64+ty*4+(i-4));
    const float* prow = P + ((size_t)(b*S_+q)*H_ + h)*NREL;
    #pragma unroll
    for (int j=0;j<8;j++){
      int kk = k0 + ((j<4)? tx*4+j : 64+tx*4+(j-4));
      int idx = kk - q;                       // pos[k]-pos[q]
      idx = idx < -R_ ? -R_ : (idx > R_ ? R_ : idx);
      float v = (acc[i][j] + prow[idx + R_]) * scale;
      Sc[((size_t)bh*S_ + q)*S_ + kk] = v;
    }
  }
}

// ---------------- softmax: one block per row of 1024 ----------------
__global__ void __launch_bounds__(256) softmax_kernel(float* __restrict__ Sc){
  size_t row = blockIdx.x;
  float* r = Sc + row*S_;
  int tid = threadIdx.x;
  float4 v = *(const float4*)(r + tid*4);
  float m = fmaxf(fmaxf(v.x,v.y), fmaxf(v.z,v.w));
  m = warp_max(m);
  __shared__ float sh[8];
  __shared__ float shm, shs;
  int w = tid>>5, lane = tid&31;
  if (lane==0) sh[w]=m;
  __syncthreads();
  if (tid==0){
    float M = sh[0];
    #pragma unroll
    for (int i=1;i<8;i++) M = fmaxf(M, sh[i]);
    shm = M;
  }
  __syncthreads();
  float M = shm;
  v.x = __expf(v.x-M); v.y = __expf(v.y-M); v.z = __expf(v.z-M); v.w = __expf(v.w-M);
  float s = v.x+v.y+v.z+v.w;
  s = warp_sum(s);
  if (lane==0) sh[w]=s;
  __syncthreads();
  if (tid==0){
    float SS=0.f;
    #pragma unroll
    for (int i=0;i<8;i++) SS += sh[i];
    shs = 1.f/SS;
  }
  __syncthreads();
  float inv = shs;
  v.x*=inv; v.y*=inv; v.z*=inv; v.w*=inv;
  *(float4*)(r + tid*4) = v;
}

// ---------------- attn @ V: per bh, [1024,1024]@[1024,64] ----------------
// grid (qtile=8, bh=64), 128x64 tile, BK=16, 8x4 per thread
__global__ void __launch_bounds__(256) attn_av(const float* __restrict__ Sc,
                                               const float* __restrict__ V,
                                               float* __restrict__ O)
{
  __shared__ float As[16][128];
  __shared__ float Bs2[16][64];
  int bh = blockIdx.y; int b = bh>>4, h = bh&15;
  int q0 = blockIdx.x*128;
  int tid = threadIdx.x, tx = tid&15, ty = tid>>4;
  float acc[8][4];
  #pragma unroll
  for (int i=0;i<8;i++)
    #pragma unroll
    for (int j=0;j<4;j++) acc[i][j]=0.f;

  int arow = tid>>1, acol = (tid&1)*8;
  int brow = tid>>4, bcol = (tid&15)*4;
  const float* Sb = Sc + ((size_t)bh*S_ + q0)*S_;
  const size_t vbase = (size_t)b*S_*D_ + h*HD_;

  for (int k0=0;k0<S_;k0+=16){
    const float* ap = Sb + (size_t)arow*S_ + k0 + acol;
    float4 a0 = *(const float4*)ap, a1 = *(const float4*)(ap+4);
    As[acol+0][arow]=a0.x; As[acol+1][arow]=a0.y; As[acol+2][arow]=a0.z; As[acol+3][arow]=a0.w;
    As[acol+4][arow]=a1.x; As[acol+5][arow]=a1.y; As[acol+6][arow]=a1.z; As[acol+7][arow]=a1.w;
    *(float4*)&Bs2[brow][bcol] = *(const float4*)(V + vbase + (size_t)(k0+brow)*D_ + bcol);
    __syncthreads();
    #pragma unroll
    for (int k=0;k<16;k++){
      float a[8], bb[4];
      *(float4*)&a[0]  = *(const float4*)&As[k][ty*4];
      *(float4*)&a[4]  = *(const float4*)&As[k][64+ty*4];
      *(float4*)&bb[0] = *(const float4*)&Bs2[k][tx*4];
      #pragma unroll
      for (int i=0;i<8;i++)
        #pragma unroll
        for (int j=0;j<4;j++) acc[i][j] = fmaf(a[i], bb[j], acc[i][j]);
    }
    __syncthreads();
  }
  #pragma unroll
  for (int i=0;i<8;i++){
    int q = q0 + ((i<4)? ty*4+i : 64+ty*4+(i-4));
    #pragma unroll
    for (int j=0;j<4;j++){
      int c = tx*4+j;
      O[vbase + (size_t)q*D_ + c] = acc[i][j];
    }
  }
}

// ---------------- launcher ----------------
extern "C" void kernel_launch(void* const* d_in, const int* in_sizes, int n_in,
                              void* d_out, int out_size)
{
  const float* x    = (const float*)d_in[0];
  const float* wq   = (const float*)d_in[1];
  const float* bq   = (const float*)d_in[2];
  const float* wk   = (const float*)d_in[3];
  const float* bk   = (const float*)d_in[4];
  const float* wv   = (const float*)d_in[5];
  const float* bv   = (const float*)d_in[6];
  const float* wo   = (const float*)d_in[7];
  const float* bo   = (const float*)d_in[8];
  const float* rel  = (const float*)d_in[9];
  const float* ln1g = (const float*)d_in[10];
  const float* ln1b = (const float*)d_in[11];
  const float* ln2g = (const float*)d_in[12];
  const float* ln2b = (const float*)d_in[13];
  const float* w1   = (const float*)d_in[14];
  const float* b1   = (const float*)d_in[15];
  const float* w2   = (const float*)d_in[16];
  const float* b2   = (const float*)d_in[17];
  float* out = (float*)d_out;

  float *h_, *q_, *k_, *v_, *relT_, *p_, *sc_, *o_, *x2_, *ff_;
  cudaGetSymbolAddress((void**)&h_,   g_h);
  cudaGetSymbolAddress((void**)&q_,   g_q);
  cudaGetSymbolAddress((void**)&k_,   g_k);
  cudaGetSymbolAddress((void**)&v_,   g_v);
  cudaGetSymbolAddress((void**)&relT_,g_relT);
  cudaGetSymbolAddress((void**)&p_,   g_p);
  cudaGetSymbolAddress((void**)&sc_,  g_sc);
  cudaGetSymbolAddress((void**)&o_,   g_o);
  cudaGetSymbolAddress((void**)&x2_,  g_x2);
  cudaGetSymbolAddress((void**)&ff_,  g_ff);

  // 1. LN1
  ln_kernel<<<BS_, 256>>>(x, ln1g, ln1b, h_);
  // 2. Q/K/V projections
  sgemm_nn<EPI_BIAS><<<dim3(8,32), 256>>>(h_, wq, bq, nullptr, q_, BS_, D_, D_);
  sgemm_nn<EPI_BIAS><<<dim3(8,32), 256>>>(h_, wk, bk, nullptr, k_, BS_, D_, D_);
  sgemm_nn<EPI_BIAS><<<dim3(8,32), 256>>>(h_, wv, bv, nullptr, v_, BS_, D_, D_);
  // 3. rel projection
  rel_transpose<<<(NREL*HD_ + 255)/256, 256>>>(rel, relT_);
  rel_proj<<<BS_, 256>>>(q_, relT_, p_);
  // 4. scores + rel gather + scale
  attn_scores<<<dim3(8,8,Bb_*H_), 256>>>(q_, k_, p_, sc_);
  // 5. softmax
  softmax_kernel<<<Bb_*H_*S_, 256>>>(sc_);
  // 6. attn @ V
  attn_av<<<dim3(8,Bb_*H_), 256>>>(sc_, v_, o_);
  // 7. output projection + residual
  sgemm_nn<EPI_BIAS_RESID><<<dim3(8,32), 256>>>(o_, wo, bo, x, x2_, BS_, D_, D_);
  // 8. LN2
  ln_kernel<<<BS_, 256>>>(x2_, ln2g, ln2b, h_);
  // 9. FFN1 + exact GELU
  sgemm_nn<EPI_BIAS_GELU><<<dim3(32,32), 256>>>(h_, w1, b1, nullptr, ff_, BS_, 4*D_, D_);
  // 10. FFN2 + residual -> out
  sgemm_nn<EPI_BIAS_RESID><<<dim3(8,32), 256>>>(ff_, w2, b2, x2_, out, BS_, D_, 4*D_);
}

// round 3
// speedup vs baseline: 1.7883x; 1.7883x over previous
#include <cuda_runtime.h>
#include <cuda_bf16.h>
#include <math.h>
#include <stdint.h>

#define Bb_ 4
#define S_ 1024
#define D_ 1024
#define H_ 16
#define HD_ 64
#define R_ 128
#define NREL 257
#define BS_ (Bb_*S_)   // 4096
#define EPSLN 1e-5f

// -------- device scratch (allocation-free rule: __device__ globals) --------
__device__ float g_h [BS_*D_];                 // LN output (reused for LN2)
__device__ float g_q [BS_*D_];
__device__ float g_k [BS_*D_];
__device__ float g_v [BS_*D_];
__device__ float g_relT[HD_*NREL];             // rel_embed transposed [d][j]
__device__ float g_p [ (size_t)BS_*H_*NREL ];  // rel projection [bs][h][j]
__device__ float g_sc[ (size_t)Bb_*H_*S_*S_ ]; // scores 256MB
__device__ float g_o [BS_*D_];                 // attention output (pre-proj)
__device__ float g_x2[BS_*D_];                 // after first residual
__device__ float g_ff[(size_t)BS_*4*D_];       // FFN intermediate
// transposed weights [N,K]
__device__ float g_wqT[D_*D_];
__device__ float g_wkT[D_*D_];
__device__ float g_wvT[D_*D_];
__device__ float g_woT[D_*D_];
__device__ float g_w1T[(size_t)D_*4*D_];
__device__ float g_w2T[(size_t)4*D_*D_];

// ---------------- helpers ----------------
__device__ __forceinline__ float warp_sum(float v){
  #pragma unroll
  for (int o=16;o>0;o>>=1) v += __shfl_xor_sync(0xffffffffu, v, o);
  return v;
}
__device__ __forceinline__ float warp_max(float v){
  #pragma unroll
  for (int o=16;o>0;o>>=1) v = fmaxf(v, __shfl_xor_sync(0xffffffffu, v, o));
  return v;
}
__device__ __forceinline__ uint32_t f2tf32(float f){
  uint32_t u; asm("cvt.rna.tf32.f32 %0, %1;" : "=r"(u) : "f"(f)); return u;
}
__device__ __forceinline__ void mma_tf32(float* d, const uint32_t* a, const uint32_t* b){
  asm volatile("mma.sync.aligned.m16n8k8.row.col.f32.tf32.tf32.f32 "
    "{%0,%1,%2,%3}, {%4,%5,%6,%7}, {%8,%9}, {%0,%1,%2,%3};"
    : "+f"(d[0]),"+f"(d[1]),"+f"(d[2]),"+f"(d[3])
    : "r"(a[0]),"r"(a[1]),"r"(a[2]),"r"(a[3]), "r"(b[0]),"r"(b[1]));
}

// ---------------- tf32 mma GEMM: C[M,N] = A[M,K] @ Bt[N,K]^T (+epi) --------
// tile 128x128x32, 8 warps (4 M x 2 N), warp tile 32x64 (2x8 m16n8k8 frags)
#define EPI_BIAS        0
#define EPI_BIAS_RESID  1
#define EPI_BIAS_GELU   2
#define AST 36   // padded row stride

template<int EPI>
__global__ void __launch_bounds__(256) mma_gemm(const float* __restrict__ A,
                                                const float* __restrict__ Bt,
                                                const float* __restrict__ bias,
                                                const float* __restrict__ resid,
                                                float* __restrict__ C,
                                                int M, int N, int K)
{
  __shared__ uint32_t As[128*AST];
  __shared__ uint32_t Bs[128*AST];
  const int tid = threadIdx.x;
  const int wid = tid >> 5, lane = tid & 31;
  const int warp_m = wid >> 1, warp_n = wid & 1;
  const int m0 = blockIdx.y*128, n0 = blockIdx.x*128;
  const int lr = lane >> 2, lc = lane & 3;

  float acc[2][8][4];
  #pragma unroll
  for (int i=0;i<2;i++)
    #pragma unroll
    for (int j=0;j<8;j++)
      #pragma unroll
      for (int t=0;t<4;t++) acc[i][j][t]=0.f;

  // global load mapping: 2 threads per row, 16 floats each
  const int grow = tid >> 1;
  const int ghalf = (tid & 1)*16;
  const float* Ag = A  + (size_t)(m0 + grow)*K + ghalf;
  const float* Bg = Bt + (size_t)(n0 + grow)*K + ghalf;
  uint32_t* as_dst = &As[grow*AST + ghalf];
  uint32_t* bs_dst = &Bs[grow*AST + ghalf];

  // fragment smem bases
  const uint32_t* a_base0 = &As[(warp_m*32 + lr)*AST + lc];
  const uint32_t* b_base  = &Bs[(warp_n*64 + lr)*AST + lc];

  for (int k0 = 0; k0 < K; k0 += 32){
    #pragma unroll
    for (int i=0;i<4;i++){
      float4 va = *(const float4*)(Ag + k0 + i*4);
      uint4 ta = make_uint4(f2tf32(va.x), f2tf32(va.y), f2tf32(va.z), f2tf32(va.w));
      *(uint4*)(as_dst + i*4) = ta;
      float4 vb = *(const float4*)(Bg + k0 + i*4);
      uint4 tb = make_uint4(f2tf32(vb.x), f2tf32(vb.y), f2tf32(vb.z), f2tf32(vb.w));
      *(uint4*)(bs_dst + i*4) = tb;
    }
    __syncthreads();
    #pragma unroll
    for (int ks=0; ks<4; ks++){
      const int kk = ks*8;
      uint32_t a[2][4], b[8][2];
      #pragma unroll
      for (int mf=0; mf<2; mf++){
        const uint32_t* ap = a_base0 + mf*16*AST + kk;
        a[mf][0] = ap[0];
        a[mf][1] = ap[8*AST];
        a[mf][2] = ap[4];
        a[mf][3] = ap[8*AST + 4];
      }
      #pragma unroll
      for (int nf=0; nf<8; nf++){
        const uint32_t* bp = b_base + nf*8*AST + kk;
        b[nf][0] = bp[0];
        b[nf][1] = bp[4];
      }
      #pragma unroll
      for (int mf=0; mf<2; mf++)
        #pragma unroll
        for (int nf=0; nf<8; nf++)
          mma_tf32(acc[mf][nf], a[mf], b[nf]);
    }
    __syncthreads();
  }

  // epilogue: c0,c1 at (row=lr, col=2lc), c2,c3 at (row=lr+8, col=2lc)
  #pragma unroll
  for (int mf=0; mf<2; mf++){
    #pragma unroll
    for (int half=0; half<2; half++){
      const int row = m0 + warp_m*32 + mf*16 + lr + half*8;
      float*       crow = C + (size_t)row*N;
      const float* rrow = (EPI == EPI_BIAS_RESID) ? (resid + (size_t)row*N) : nullptr;
      #pragma unroll
      for (int nf=0; nf<8; nf++){
        const int col = n0 + warp_n*64 + nf*8 + 2*lc;
        float v0 = acc[mf][nf][half*2 + 0] + bias[col];
        float v1 = acc[mf][nf][half*2 + 1] + bias[col+1];
        if (EPI == EPI_BIAS_RESID){ v0 += rrow[col]; v1 += rrow[col+1]; }
        if (EPI == EPI_BIAS_GELU){
          v0 = 0.5f*v0*(1.0f + erff(v0*0.70710678118654752f));
          v1 = 0.5f*v1*(1.0f + erff(v1*0.70710678118654752f));
        }
        *(float2*)(crow + col) = make_float2(v0, v1);
      }
    }
  }
}

// ---------------- weight transpose: W[Kd,Nd] -> Wt[Nd,Kd] ----------------
__global__ void __launch_bounds__(256) transpose_k(const float* __restrict__ W,
                                                   float* __restrict__ Wt,
                                                   int Kd, int Nd)
{
  __shared__ float t[32][33];
  int n = blockIdx.x*32 + threadIdx.x;
  int k = blockIdx.y*32 + threadIdx.y;
  #pragma unroll
  for (int i=0;i<32;i+=8)
    t[threadIdx.y+i][threadIdx.x] = W[(size_t)(k+i)*Nd + n];
  __syncthreads();
  int n2 = blockIdx.x*32 + threadIdx.y;
  int k2 = blockIdx.y*32 + threadIdx.x;
  #pragma unroll
  for (int i=0;i<32;i+=8)
    Wt[(size_t)(n2+i)*Kd + k2] = t[threadIdx.x][threadIdx.y+i];
}

// ---------------- LayerNorm ----------------
__global__ void __launch_bounds__(256) ln_kernel(const float* __restrict__ x,
                                                 const float* __restrict__ g,
                                                 const float* __restrict__ bta,
                                                 float* __restrict__ y)
{
  int row = blockIdx.x;
  int tid = threadIdx.x;
  const float* xr = x + (size_t)row*D_;
  float4 v = *(const float4*)(xr + tid*4);
  float s  = v.x+v.y+v.z+v.w;
  float ss = v.x*v.x+v.y*v.y+v.z*v.z+v.w*v.w;
  s = warp_sum(s); ss = warp_sum(ss);
  __shared__ float sh[16];
  __shared__ float sh_mu, sh_rs;
  int w = tid>>5, lane = tid&31;
  if (lane==0){ sh[w]=s; sh[8+w]=ss; }
  __syncthreads();
  if (tid==0){
    float S=0.f, SS=0.f;
    #pragma unroll
    for (int i=0;i<8;i++){ S+=sh[i]; SS+=sh[8+i]; }
    float mu  = S*(1.f/(float)D_);
    float var = SS*(1.f/(float)D_) - mu*mu;
    sh_mu = mu; sh_rs = rsqrtf(var + EPSLN);
  }
  __syncthreads();
  float mu = sh_mu, rs = sh_rs;
  float4 gv = *(const float4*)(g   + tid*4);
  float4 bv = *(const float4*)(bta + tid*4);
  float4 o;
  o.x = (v.x-mu)*rs*gv.x + bv.x;
  o.y = (v.y-mu)*rs*gv.y + bv.y;
  o.z = (v.z-mu)*rs*gv.z + bv.z;
  o.w = (v.w-mu)*rs*gv.w + bv.w;
  *(float4*)(y + (size_t)row*D_ + tid*4) = o;
}

// ---------------- rel_embed transpose ----------------
__global__ void rel_transpose(const float* __restrict__ rel, float* __restrict__ relT){
  int i = blockIdx.x*256 + threadIdx.x;
  if (i < NREL*HD_){
    int j = i / HD_, d = i % HD_;
    relT[d*NREL + j] = rel[i];
  }
}

// ---------------- rel projection ----------------
__global__ void __launch_bounds__(256) rel_proj(const float* __restrict__ Q,
                                                const float* __restrict__ relT,
                                                float* __restrict__ P)
{
  int bs = blockIdx.x;
  __shared__ float sq[D_];
  int tid = threadIdx.x;
  *(float4*)&sq[tid*4] = *(const float4*)(Q + (size_t)bs*D_ + tid*4);
  __syncthreads();

  int hg = tid >> 6;
  int jt = tid & 63;
  float acc[4][5];
  #pragma unroll
  for (int a=0;a<4;a++)
    #pragma unroll
    for (int g=0;g<5;g++) acc[a][g]=0.f;

  for (int d=0; d<HD_; d++){
    const float* rrow = relT + d*NREL;
    float rv[5];
    #pragma unroll
    for (int g=0; g<4; g++) rv[g] = __ldg(rrow + jt + 64*g);
    rv[4] = (jt==0) ? __ldg(rrow + 256) : 0.f;
    #pragma unroll
    for (int hh=0; hh<4; hh++){
      float qv = sq[(hg + 4*hh)*HD_ + d];
      #pragma unroll
      for (int g=0; g<5; g++) acc[hh][g] = fmaf(qv, rv[g], acc[hh][g]);
    }
  }
  #pragma unroll
  for (int hh=0; hh<4; hh++){
    int h = hg + 4*hh;
    float* prow = P + ((size_t)bs*H_ + h)*NREL;
    #pragma unroll
    for (int g=0; g<4; g++) prow[jt + 64*g] = acc[hh][g];
    if (jt==0) prow[256] = acc[hh][4];
  }
}

// ---------------- attention scores ----------------
__global__ void __launch_bounds__(256) attn_scores(const float* __restrict__ Q,
                                                   const float* __restrict__ Kt,
                                                   const float* __restrict__ P,
                                                   float* __restrict__ Sc)
{
  __shared__ float Qs[16][128];
  __shared__ float Ks[16][128];
  int bh = blockIdx.z; int b = bh >> 4, h = bh & 15;
  int q0 = blockIdx.y*128, k0 = blockIdx.x*128;
  int tid = threadIdx.x, tx = tid&15, ty = tid>>4;
  const size_t base = (size_t)b*S_*D_ + h*HD_;
  int lrow = tid>>1;
  int lcol = (tid&1)*8;
  float acc[8][8];
  #pragma unroll
  for (int i=0;i<8;i++)
    #pragma unroll
    for (int j=0;j<8;j++) acc[i][j]=0.f;

  for (int d0=0; d0<HD_; d0+=16){
    const float* qp = Q + base + (size_t)(q0+lrow)*D_ + d0 + lcol;
    float4 v0 = *(const float4*)qp, v1 = *(const float4*)(qp+4);
    Qs[lcol+0][lrow]=v0.x; Qs[lcol+1][lrow]=v0.y; Qs[lcol+2][lrow]=v0.z; Qs[lcol+3][lrow]=v0.w;
    Qs[lcol+4][lrow]=v1.x; Qs[lcol+5][lrow]=v1.y; Qs[lcol+6][lrow]=v1.z; Qs[lcol+7][lrow]=v1.w;
    const float* kp = Kt + base + (size_t)(k0+lrow)*D_ + d0 + lcol;
    float4 w0 = *(const float4*)kp, w1 = *(const float4*)(kp+4);
    Ks[lcol+0][lrow]=w0.x; Ks[lcol+1][lrow]=w0.y; Ks[lcol+2][lrow]=w0.z; Ks[lcol+3][lrow]=w0.w;
    Ks[lcol+4][lrow]=w1.x; Ks[lcol+5][lrow]=w1.y; Ks[lcol+6][lrow]=w1.z; Ks[lcol+7][lrow]=w1.w;
    __syncthreads();
    #pragma unroll
    for (int k=0;k<16;k++){
      float a[8], bb[8];
      *(float4*)&a[0]  = *(const float4*)&Qs[k][ty*4];
      *(float4*)&a[4]  = *(const float4*)&Qs[k][64+ty*4];
      *(float4*)&bb[0] = *(const float4*)&Ks[k][tx*4];
      *(float4*)&bb[4] = *(const float4*)&Ks[k][64+tx*4];
      #pragma unroll
      for (int i=0;i<8;i++)
        #pragma unroll
        for (int j=0;j<8;j++) acc[i][j] = fmaf(a[i], bb[j], acc[i][j]);
    }
    __syncthreads();
  }

  const float scale = 0.125f;
  #pragma unroll
  for (int i=0;i<8;i++){
    int q = q0 + ((i<4)? ty*4+i : 64+ty*4+(i-4));
    const float* prow = P + ((size_t)(b*S_+q)*H_ + h)*NREL;
    #pragma unroll
    for (int j=0;j<8;j++){
      int kk = k0 + ((j<4)? tx*4+j : 64+tx*4+(j-4));
      int idx = kk - q;
      idx = idx < -R_ ? -R_ : (idx > R_ ? R_ : idx);
      float v = (acc[i][j] + prow[idx + R_]) * scale;
      Sc[((size_t)bh*S_ + q)*S_ + kk] = v;
    }
  }
}

// ---------------- softmax ----------------
__global__ void __launch_bounds__(256) softmax_kernel(float* __restrict__ Sc){
  size_t row = blockIdx.x;
  float* r = Sc + row*S_;
  int tid = threadIdx.x;
  float4 v = *(const float4*)(r + tid*4);
  float m = fmaxf(fmaxf(v.x,v.y), fmaxf(v.z,v.w));
  m = warp_max(m);
  __shared__ float sh[8];
  __shared__ float shm, shs;
  int w = tid>>5, lane = tid&31;
  if (lane==0) sh[w]=m;
  __syncthreads();
  if (tid==0){
    float M = sh[0];
    #pragma unroll
    for (int i=1;i<8;i++) M = fmaxf(M, sh[i]);
    shm = M;
  }
  __syncthreads();
  float M = shm;
  v.x = __expf(v.x-M); v.y = __expf(v.y-M); v.z = __expf(v.z-M); v.w = __expf(v.w-M);
  float s = v.x+v.y+v.z+v.w;
  s = warp_sum(s);
  if (lane==0) sh[w]=s;
  __syncthreads();
  if (tid==0){
    float SS=0.f;
    #pragma unroll
    for (int i=0;i<8;i++) SS += sh[i];
    shs = 1.f/SS;
  }
  __syncthreads();
  float inv = shs;
  v.x*=inv; v.y*=inv; v.z*=inv; v.w*=inv;
  *(float4*)(r + tid*4) = v;
}

// ---------------- attn @ V ----------------
__global__ void __launch_bounds__(256) attn_av(const float* __restrict__ Sc,
                                               const float* __restrict__ V,
                                               float* __restrict__ O)
{
  __shared__ float As2[16][128];
  __shared__ float Bs2[16][64];
  int bh = blockIdx.y; int b = bh>>4, h = bh&15;
  int q0 = blockIdx.x*128;
  int tid = threadIdx.x, tx = tid&15, ty = tid>>4;
  float acc[8][4];
  #pragma unroll
  for (int i=0;i<8;i++)
    #pragma unroll
    for (int j=0;j<4;j++) acc[i][j]=0.f;

  int arow = tid>>1, acol = (tid&1)*8;
  int brow = tid>>4, bcol = (tid&15)*4;
  const float* Sb = Sc + ((size_t)bh*S_ + q0)*S_;
  const size_t vbase = (size_t)b*S_*D_ + h*HD_;

  for (int k0=0;k0<S_;k0+=16){
    const float* ap = Sb + (size_t)arow*S_ + k0 + acol;
    float4 a0 = *(const float4*)ap, a1 = *(const float4*)(ap+4);
    As2[acol+0][arow]=a0.x; As2[acol+1][arow]=a0.y; As2[acol+2][arow]=a0.z; As2[acol+3][arow]=a0.w;
    As2[acol+4][arow]=a1.x; As2[acol+5][arow]=a1.y; As2[acol+6][arow]=a1.z; As2[acol+7][arow]=a1.w;
    *(float4*)&Bs2[brow][bcol] = *(const float4*)(V + vbase + (size_t)(k0+brow)*D_ + bcol);
    __syncthreads();
    #pragma unroll
    for (int k=0;k<16;k++){
      float a[8], bb[4];
      *(float4*)&a[0]  = *(const float4*)&As2[k][ty*4];
      *(float4*)&a[4]  = *(const float4*)&As2[k][64+ty*4];
      *(float4*)&bb[0] = *(const float4*)&Bs2[k][tx*4];
      #pragma unroll
      for (int i=0;i<8;i++)
        #pragma unroll
        for (int j=0;j<4;j++) acc[i][j] = fmaf(a[i], bb[j], acc[i][j]);
    }
    __syncthreads();
  }
  #pragma unroll
  for (int i=0;i<8;i++){
    int q = q0 + ((i<4)? ty*4+i : 64+ty*4+(i-4));
    #pragma unroll
    for (int j=0;j<4;j++){
      int c = tx*4+j;
      O[vbase + (size_t)q*D_ + c] = acc[i][j];
    }
  }
}

// ---------------- launcher ----------------
extern "C" void kernel_launch(void* const* d_in, const int* in_sizes, int n_in,
                              void* d_out, int out_size)
{
  const float* x    = (const float*)d_in[0];
  const float* wq   = (const float*)d_in[1];
  const float* bq   = (const float*)d_in[2];
  const float* wk   = (const float*)d_in[3];
  const float* bk   = (const float*)d_in[4];
  const float* wv   = (const float*)d_in[5];
  const float* bv   = (const float*)d_in[6];
  const float* wo   = (const float*)d_in[7];
  const float* bo   = (const float*)d_in[8];
  const float* rel  = (const float*)d_in[9];
  const float* ln1g = (const float*)d_in[10];
  const float* ln1b = (const float*)d_in[11];
  const float* ln2g = (const float*)d_in[12];
  const float* ln2b = (const float*)d_in[13];
  const float* w1   = (const float*)d_in[14];
  const float* b1   = (const float*)d_in[15];
  const float* w2   = (const float*)d_in[16];
  const float* b2   = (const float*)d_in[17];
  float* out = (float*)d_out;

  float *h_, *q_, *k_, *v_, *relT_, *p_, *sc_, *o_, *x2_, *ff_;
  float *wqT_, *wkT_, *wvT_, *woT_, *w1T_, *w2T_;
  cudaGetSymbolAddress((void**)&h_,   g_h);
  cudaGetSymbolAddress((void**)&q_,   g_q);
  cudaGetSymbolAddress((void**)&k_,   g_k);
  cudaGetSymbolAddress((void**)&v_,   g_v);
  cudaGetSymbolAddress((void**)&relT_,g_relT);
  cudaGetSymbolAddress((void**)&p_,   g_p);
  cudaGetSymbolAddress((void**)&sc_,  g_sc);
  cudaGetSymbolAddress((void**)&o_,   g_o);
  cudaGetSymbolAddress((void**)&x2_,  g_x2);
  cudaGetSymbolAddress((void**)&ff_,  g_ff);
  cudaGetSymbolAddress((void**)&wqT_, g_wqT);
  cudaGetSymbolAddress((void**)&wkT_, g_wkT);
  cudaGetSymbolAddress((void**)&wvT_, g_wvT);
  cudaGetSymbolAddress((void**)&woT_, g_woT);
  cudaGetSymbolAddress((void**)&w1T_, g_w1T);
  cudaGetSymbolAddress((void**)&w2T_, g_w2T);

  // 0. weight transposes
  transpose_k<<<dim3(D_/32,   D_/32),  dim3(32,8)>>>(wq, wqT_, D_,   D_);
  transpose_k<<<dim3(D_/32,   D_/32),  dim3(32,8)>>>(wk, wkT_, D_,   D_);
  transpose_k<<<dim3(D_/32,   D_/32),  dim3(32,8)>>>(wv, wvT_, D_,   D_);
  transpose_k<<<dim3(D_/32,   D_/32),  dim3(32,8)>>>(wo, woT_, D_,   D_);
  transpose_k<<<dim3(4*D_/32, D_/32),  dim3(32,8)>>>(w1, w1T_, D_,   4*D_);
  transpose_k<<<dim3(D_/32,   4*D_/32),dim3(32,8)>>>(w2, w2T_, 4*D_, D_);

  // 1. LN1
  ln_kernel<<<BS_, 256>>>(x, ln1g, ln1b, h_);
  // 2. Q/K/V projections (legacy tensor mma, tf32)
  mma_gemm<EPI_BIAS><<<dim3(8,32), 256>>>(h_, wqT_, bq, nullptr, q_, BS_, D_, D_);
  mma_gemm<EPI_BIAS><<<dim3(8,32), 256>>>(h_, wkT_, bk, nullptr, k_, BS_, D_, D_);
  mma_gemm<EPI_BIAS><<<dim3(8,32), 256>>>(h_, wvT_, bv, nullptr, v_, BS_, D_, D_);
  // 3. rel projection
  rel_transpose<<<(NREL*HD_ + 255)/256, 256>>>(rel, relT_);
  rel_proj<<<BS_, 256>>>(q_, relT_, p_);
  // 4. scores + rel gather + scale
  attn_scores<<<dim3(8,8,Bb_*H_), 256>>>(q_, k_, p_, sc_);
  // 5. softmax
  softmax_kernel<<<Bb_*H_*S_, 256>>>(sc_);
  // 6. attn @ V
  attn_av<<<dim3(8,Bb_*H_), 256>>>(sc_, v_, o_);
  // 7. output projection + residual
  mma_gemm<EPI_BIAS_RESID><<<dim3(8,32), 256>>>(o_, woT_, bo, x, x2_, BS_, D_, D_);
  // 8. LN2
  ln_kernel<<<BS_, 256>>>(x2_, ln2g, ln2b, h_);
  // 9. FFN1 + exact GELU
  mma_gemm<EPI_BIAS_GELU><<<dim3(32,32), 256>>>(h_, w1T_, b1, nullptr, ff_, BS_, 4*D_, D_);
  // 10. FFN2 + residual -> out
  mma_gemm<EPI_BIAS_RESID><<<dim3(8,32), 256>>>(ff_, w2T_, b2, x2_, out, BS_, D_, 4*D_);
}

// round 4
// speedup vs baseline: 2.0850x; 1.1659x over previous
#include <cuda_runtime.h>
#include <cuda_bf16.h>
#include <math.h>
#include <stdint.h>

#define Bb_ 4
#define S_ 1024
#define D_ 1024
#define H_ 16
#define HD_ 64
#define R_ 128
#define NREL 257
#define BS_ (Bb_*S_)   // 4096
#define EPSLN 1e-5f

// -------- device scratch --------
__device__ float g_h [BS_*D_];
__device__ float g_q [BS_*D_];
__device__ float g_k [BS_*D_];
__device__ float g_v [BS_*D_];
__device__ float g_relT[HD_*NREL];
__device__ float g_p [ (size_t)BS_*H_*NREL ];
__device__ float g_sc[ (size_t)Bb_*H_*S_*S_ ];
__device__ float g_o [BS_*D_];
__device__ float g_x2[BS_*D_];
__device__ float g_ff[(size_t)BS_*4*D_];
__device__ float g_wqT[D_*D_];
__device__ float g_wkT[D_*D_];
__device__ float g_wvT[D_*D_];
__device__ float g_woT[D_*D_];
__device__ float g_w1T[(size_t)D_*4*D_];
__device__ float g_w2T[(size_t)4*D_*D_];

// ---------------- helpers ----------------
__device__ __forceinline__ float warp_sum(float v){
  #pragma unroll
  for (int o=16;o>0;o>>=1) v += __shfl_xor_sync(0xffffffffu, v, o);
  return v;
}
__device__ __forceinline__ float warp_max(float v){
  #pragma unroll
  for (int o=16;o>0;o>>=1) v = fmaxf(v, __shfl_xor_sync(0xffffffffu, v, o));
  return v;
}
__device__ __forceinline__ float tf32r(float f){
  uint32_t u; asm("cvt.rna.tf32.f32 %0, %1;" : "=r"(u) : "f"(f));
  return __uint_as_float(u);
}
__device__ __forceinline__ void mma_tf32(float* d, const uint32_t* a, const uint32_t* b){
  asm volatile("mma.sync.aligned.m16n8k8.row.col.f32.tf32.tf32.f32 "
    "{%0,%1,%2,%3}, {%4,%5,%6,%7}, {%8,%9}, {%0,%1,%2,%3};"
    : "+f"(d[0]),"+f"(d[1]),"+f"(d[2]),"+f"(d[3])
    : "r"(a[0]),"r"(a[1]),"r"(a[2]),"r"(a[3]), "r"(b[0]),"r"(b[1]));
}
__device__ __forceinline__ void cp16(uint32_t dst, const void* src){
  asm volatile("cp.async.cg.shared.global [%0], [%1], 16;" :: "r"(dst), "l"(src));
}
#define CP_COMMIT() asm volatile("cp.async.commit_group;" ::: "memory")
#define CP_WAIT1()  asm volatile("cp.async.wait_group 1;" ::: "memory")
#define CP_WAIT0()  asm volatile("cp.async.wait_group 0;" ::: "memory")

#define EPI_BIAS        0
#define EPI_BIAS_RESID  1
#define EPI_BIAS_GELU   2
#define AST 36
#define ABYTES (128*AST*4)

// ---------------- pipelined tf32 mma GEMM: C = A[M,K] @ Bt[N,K]^T (+epi) ----
// 128x128x32 tile, 3-stage cp.async, 8 warps (4x2), warp 32x64
template<int EPI, int RND>
__global__ void __launch_bounds__(256) mma_gemm(const float* __restrict__ A,
                                                const float* __restrict__ Bt,
                                                const float* __restrict__ bias,
                                                const float* __restrict__ resid,
                                                float* __restrict__ C,
                                                int M, int N, int K)
{
  extern __shared__ char sm[];
  float* Asm = (float*)sm;                 // 3 stages of 128*36
  float* Bsm = (float*)(sm + 3*ABYTES);    // 3 stages of 128*36
  const int tid = threadIdx.x;
  const int wid = tid >> 5, lane = tid & 31;
  const int warp_m = wid >> 1, warp_n = wid & 1;
  const int m0 = blockIdx.y*128, n0 = blockIdx.x*128;
  const int lr = lane >> 2, lc = lane & 3;
  const int grow = tid >> 1, gh = (tid & 1)*16;

  const float* Ag = A  + (size_t)(m0 + grow)*K + gh;
  const float* Bg = Bt + (size_t)(n0 + grow)*K + gh;
  const uint32_t a_s = (uint32_t)__cvta_generic_to_shared(Asm) + (grow*AST + gh)*4;
  const uint32_t b_s = (uint32_t)__cvta_generic_to_shared(Bsm) + (grow*AST + gh)*4;

  float acc[2][8][4];
  #pragma unroll
  for (int i=0;i<2;i++)
    #pragma unroll
    for (int j=0;j<8;j++)
      #pragma unroll
      for (int t=0;t<4;t++) acc[i][j][t]=0.f;

  const int NC = K >> 5;
  auto load = [&](int c, int s){
    const float* ga = Ag + c*32;
    const float* gb = Bg + c*32;
    const uint32_t da = a_s + s*ABYTES;
    const uint32_t db = b_s + s*ABYTES;
    #pragma unroll
    for (int i=0;i<4;i++){
      cp16(da + i*16, ga + i*4);
      cp16(db + i*16, gb + i*4);
    }
  };

  load(0,0); CP_COMMIT();
  if (NC > 1) load(1,1);
  CP_COMMIT();

  for (int c = 0; c < NC; c++){
    const int s = c - (c/3)*3;
    if (c + 1 < NC) CP_WAIT1(); else CP_WAIT0();
    __syncthreads();
    const uint32_t* As_ = (const uint32_t*)Asm + s*(ABYTES/4) + (warp_m*32 + lr)*AST + lc;
    const uint32_t* Bs_ = (const uint32_t*)Bsm + s*(ABYTES/4) + (warp_n*64 + lr)*AST + lc;
    #pragma unroll
    for (int ks=0; ks<4; ks++){
      const int kk = ks*8;
      uint32_t a[2][4], b[8][2];
      #pragma unroll
      for (int mf=0; mf<2; mf++){
        const uint32_t* ap = As_ + mf*16*AST + kk;
        a[mf][0] = ap[0];
        a[mf][1] = ap[8*AST];
        a[mf][2] = ap[4];
        a[mf][3] = ap[8*AST + 4];
      }
      #pragma unroll
      for (int nf=0; nf<8; nf++){
        const uint32_t* bp = Bs_ + nf*8*AST + kk;
        b[nf][0] = bp[0];
        b[nf][1] = bp[4];
      }
      #pragma unroll
      for (int mf=0; mf<2; mf++)
        #pragma unroll
        for (int nf=0; nf<8; nf++)
          mma_tf32(acc[mf][nf], a[mf], b[nf]);
    }
    if (c + 2 < NC) load(c+2, (c+2) - ((c+2)/3)*3);
    CP_COMMIT();
  }

  // epilogue
  #pragma unroll
  for (int mf=0; mf<2; mf++){
    #pragma unroll
    for (int half=0; half<2; half++){
      const int row = m0 + warp_m*32 + mf*16 + lr + half*8;
      float*       crow = C + (size_t)row*N;
      const float* rrow = (EPI == EPI_BIAS_RESID) ? (resid + (size_t)row*N) : nullptr;
      #pragma unroll
      for (int nf=0; nf<8; nf++){
        const int col = n0 + warp_n*64 + nf*8 + 2*lc;
        float v0 = acc[mf][nf][half*2 + 0] + bias[col];
        float v1 = acc[mf][nf][half*2 + 1] + bias[col+1];
        if (EPI == EPI_BIAS_RESID){ v0 += rrow[col]; v1 += rrow[col+1]; }
        if (EPI == EPI_BIAS_GELU){
          v0 = 0.5f*v0*(1.0f + erff(v0*0.70710678118654752f));
          v1 = 0.5f*v1*(1.0f + erff(v1*0.70710678118654752f));
        }
        if (RND){ v0 = tf32r(v0); v1 = tf32r(v1); }
        *(float2*)(crow + col) = make_float2(v0, v1);
      }
    }
  }
}

// ---------------- attention scores on mma: Sc = (Q·K^T + bias)*scale -------
// grid (kt=8, qt=8, bh=64), CTA 128x128, K=64 one shot, stride 68
__global__ void __launch_bounds__(256) attn_scores_mma(const float* __restrict__ Q,
                                                       const float* __restrict__ Kt,
                                                       const float* __restrict__ P,
                                                       float* __restrict__ Sc)
{
  extern __shared__ float smf[];
  float* Qs = smf;             // 128*68
  float* Ks = smf + 128*68;
  const int bh = blockIdx.z, b = bh >> 4, h = bh & 15;
  const int q0 = blockIdx.y*128, k0 = blockIdx.x*128;
  const int tid = threadIdx.x, wid = tid >> 5, lane = tid & 31;
  const int warp_m = wid >> 1, warp_n = wid & 1;
  const int lr = lane >> 2, lc = lane & 3;
  const size_t base = (size_t)b*S_*D_ + h*HD_;
  const int row = tid >> 1, half = (tid & 1)*32;

  const float* qp = Q  + base + (size_t)(q0 + row)*D_ + half;
  const float* kp = Kt + base + (size_t)(k0 + row)*D_ + half;
  #pragma unroll
  for (int i=0;i<8;i++){
    *(float4*)&Qs[row*68 + half + i*4] = *(const float4*)(qp + i*4);
    *(float4*)&Ks[row*68 + half + i*4] = *(const float4*)(kp + i*4);
  }
  __syncthreads();

  float acc[2][8][4];
  #pragma unroll
  for (int i=0;i<2;i++)
    #pragma unroll
    for (int j=0;j<8;j++)
      #pragma unroll
      for (int t=0;t<4;t++) acc[i][j][t]=0.f;

  const uint32_t* a_base = (const uint32_t*)Qs + (warp_m*32 + lr)*68 + lc;
  const uint32_t* b_base = (const uint32_t*)Ks + (warp_n*64 + lr)*68 + lc;
  #pragma unroll
  for (int ks=0; ks<8; ks++){
    const int kk = ks*8;
    uint32_t a[2][4], b[8][2];
    #pragma unroll
    for (int mf=0; mf<2; mf++){
      const uint32_t* ap = a_base + mf*16*68 + kk;
      a[mf][0] = ap[0];
      a[mf][1] = ap[8*68];
      a[mf][2] = ap[4];
      a[mf][3] = ap[8*68 + 4];
    }
    #pragma unroll
    for (int nf=0; nf<8; nf++){
      const uint32_t* bp = b_base + nf*8*68 + kk;
      b[nf][0] = bp[0];
      b[nf][1] = bp[4];
    }
    #pragma unroll
    for (int mf=0; mf<2; mf++)
      #pragma unroll
      for (int nf=0; nf<8; nf++)
        mma_tf32(acc[mf][nf], a[mf], b[nf]);
  }

  const float scale = 0.125f;
  #pragma unroll
  for (int mf=0; mf<2; mf++){
    #pragma unroll
    for (int hf=0; hf<2; hf++){
      const int q = q0 + warp_m*32 + mf*16 + hf*8 + lr;
      const float* prow = P + ((size_t)(b*S_ + q)*H_ + h)*NREL;
      float* srow = Sc + ((size_t)bh*S_ + q)*S_;
      #pragma unroll
      for (int nf=0; nf<8; nf++){
        const int col = k0 + warp_n*64 + nf*8 + 2*lc;
        int i0 = col - q;     i0 = i0 < -R_ ? -R_ : (i0 > R_ ? R_ : i0);
        int i1 = col + 1 - q; i1 = i1 < -R_ ? -R_ : (i1 > R_ ? R_ : i1);
        float v0 = (acc[mf][nf][hf*2 + 0] + prow[i0 + R_]) * scale;
        float v1 = (acc[mf][nf][hf*2 + 1] + prow[i1 + R_]) * scale;
        *(float2*)(srow + col) = make_float2(v0, v1);
      }
    }
  }
}

// ---------------- attn @ V on mma (pipelined): O = P[128,1024] @ V[1024,64] -
#define PB_ (128*AST*4)      // 18432
#define VST 68
#define VB_ (32*VST*4)       // 8704
__global__ void __launch_bounds__(256) attn_av_mma(const float* __restrict__ Sc,
                                                   const float* __restrict__ V,
                                                   float* __restrict__ O)
{
  extern __shared__ char sm[];
  float* Ps = (float*)sm;                // 3 stages of 128*36
  float* Vs = (float*)(sm + 3*PB_);      // 3 stages of 32*68
  const int bh = blockIdx.y, b = bh >> 4, h = bh & 15;
  const int q0 = blockIdx.x*128;
  const int tid = threadIdx.x, wid = tid >> 5, lane = tid & 31;
  const int lr = lane >> 2, lc = lane & 3;
  const float* Sb = Sc + ((size_t)bh*S_ + q0)*S_;
  const size_t vbase = (size_t)b*S_*D_ + h*HD_;

  const int prow = tid >> 1, ph = (tid & 1)*16;
  const int vrow = tid >> 3, vcol = (tid & 7)*8;
  const uint32_t p_s = (uint32_t)__cvta_generic_to_shared(Ps) + (prow*AST + ph)*4;
  const uint32_t v_s = (uint32_t)__cvta_generic_to_shared(Vs) + (vrow*VST + vcol)*4;

  float acc[8][4];
  #pragma unroll
  for (int j=0;j<8;j++)
    #pragma unroll
    for (int t=0;t<4;t++) acc[j][t]=0.f;

  auto load = [&](int c, int s){
    const float* gp = Sb + (size_t)prow*S_ + c*32 + ph;
    const uint32_t dp = p_s + s*PB_;
    #pragma unroll
    for (int i=0;i<4;i++) cp16(dp + i*16, gp + i*4);
    const float* gv = V + vbase + (size_t)(c*32 + vrow)*D_ + vcol;
    const uint32_t dv = v_s + s*VB_;
    cp16(dv,      gv);
    cp16(dv + 16, gv + 4);
  };

  const int NC = S_ >> 5;  // 32
  load(0,0); CP_COMMIT();
  load(1,1); CP_COMMIT();

  for (int c = 0; c < NC; c++){
    const int s = c - (c/3)*3;
    if (c + 1 < NC) CP_WAIT1(); else CP_WAIT0();
    __syncthreads();
    const uint32_t* Pa = (const uint32_t*)Ps + s*(PB_/4) + (wid*16 + lr)*AST + lc;
    const uint32_t* Vb = (const uint32_t*)Vs + s*(VB_/4);
    #pragma unroll
    for (int ks=0; ks<4; ks++){
      const int kk = ks*8;
      uint32_t a[4], bfr[8][2];
      a[0] = Pa[kk];
      a[1] = Pa[8*AST + kk];
      a[2] = Pa[kk + 4];
      a[3] = Pa[8*AST + kk + 4];
      #pragma unroll
      for (int nf=0; nf<8; nf++){
        bfr[nf][0] = Vb[(kk + lc)*VST     + nf*8 + lr];
        bfr[nf][1] = Vb[(kk + lc + 4)*VST + nf*8 + lr];
      }
      #pragma unroll
      for (int nf=0; nf<8; nf++)
        mma_tf32(acc[nf], a, bfr[nf]);
    }
    if (c + 2 < NC) load(c+2, (c+2) - ((c+2)/3)*3);
    CP_COMMIT();
  }

  #pragma unroll
  for (int hf=0; hf<2; hf++){
    const int q = q0 + wid*16 + hf*8 + lr;
    float* orow = O + vbase + (size_t)q*D_;
    #pragma unroll
    for (int nf=0; nf<8; nf++){
      const int col = nf*8 + 2*lc;
      float v0 = tf32r(acc[nf][hf*2 + 0]);
      float v1 = tf32r(acc[nf][hf*2 + 1]);
      *(float2*)(orow + col) = make_float2(v0, v1);
    }
  }
}

// ---------------- weight transpose (+rna round) ----------------
__global__ void __launch_bounds__(256) transpose_k(const float* __restrict__ W,
                                                   float* __restrict__ Wt,
                                                   int Kd, int Nd)
{
  __shared__ float t[32][33];
  int n = blockIdx.x*32 + threadIdx.x;
  int k = blockIdx.y*32 + threadIdx.y;
  #pragma unroll
  for (int i=0;i<32;i+=8)
    t[threadIdx.y+i][threadIdx.x] = W[(size_t)(k+i)*Nd + n];
  __syncthreads();
  int n2 = blockIdx.x*32 + threadIdx.y;
  int k2 = blockIdx.y*32 + threadIdx.x;
  #pragma unroll
  for (int i=0;i<32;i+=8)
    Wt[(size_t)(n2+i)*Kd + k2] = tf32r(t[threadIdx.x][threadIdx.y+i]);
}

// ---------------- LayerNorm (+rna round: output feeds MMA) ----------------
__global__ void __launch_bounds__(256) ln_kernel(const float* __restrict__ x,
                                                 const float* __restrict__ g,
                                                 const float* __restrict__ bta,
                                                 float* __restrict__ y)
{
  int row = blockIdx.x;
  int tid = threadIdx.x;
  const float* xr = x + (size_t)row*D_;
  float4 v = *(const float4*)(xr + tid*4);
  float s  = v.x+v.y+v.z+v.w;
  float ss = v.x*v.x+v.y*v.y+v.z*v.z+v.w*v.w;
  s = warp_sum(s); ss = warp_sum(ss);
  __shared__ float sh[16];
  __shared__ float sh_mu, sh_rs;
  int w = tid>>5, lane = tid&31;
  if (lane==0){ sh[w]=s; sh[8+w]=ss; }
  __syncthreads();
  if (tid==0){
    float S=0.f, SS=0.f;
    #pragma unroll
    for (int i=0;i<8;i++){ S+=sh[i]; SS+=sh[8+i]; }
    float mu  = S*(1.f/(float)D_);
    float var = SS*(1.f/(float)D_) - mu*mu;
    sh_mu = mu; sh_rs = rsqrtf(var + EPSLN);
  }
  __syncthreads();
  float mu = sh_mu, rs = sh_rs;
  float4 gv = *(const float4*)(g   + tid*4);
  float4 bv = *(const float4*)(bta + tid*4);
  float4 o;
  o.x = tf32r((v.x-mu)*rs*gv.x + bv.x);
  o.y = tf32r((v.y-mu)*rs*gv.y + bv.y);
  o.z = tf32r((v.z-mu)*rs*gv.z + bv.z);
  o.w = tf32r((v.w-mu)*rs*gv.w + bv.w);
  *(float4*)(y + (size_t)row*D_ + tid*4) = o;
}

// ---------------- rel_embed transpose ----------------
__global__ void rel_transpose(const float* __restrict__ rel, float* __restrict__ relT){
  int i = blockIdx.x*256 + threadIdx.x;
  if (i < NREL*HD_){
    int j = i / HD_, d = i % HD_;
    relT[d*NREL + j] = rel[i];
  }
}

// ---------------- rel projection (fp32) ----------------
__global__ void __launch_bounds__(256) rel_proj(const float* __restrict__ Q,
                                                const float* __restrict__ relT,
                                                float* __restrict__ P)
{
  int bs = blockIdx.x;
  __shared__ float sq[D_];
  int tid = threadIdx.x;
  *(float4*)&sq[tid*4] = *(const float4*)(Q + (size_t)bs*D_ + tid*4);
  __syncthreads();

  int hg = tid >> 6;
  int jt = tid & 63;
  float acc[4][5];
  #pragma unroll
  for (int a=0;a<4;a++)
    #pragma unroll
    for (int g=0;g<5;g++) acc[a][g]=0.f;

  for (int d=0; d<HD_; d++){
    const float* rrow = relT + d*NREL;
    float rv[5];
    #pragma unroll
    for (int g=0; g<4; g++) rv[g] = __ldg(rrow + jt + 64*g);
    rv[4] = (jt==0) ? __ldg(rrow + 256) : 0.f;
    #pragma unroll
    for (int hh=0; hh<4; hh++){
      float qv = sq[(hg + 4*hh)*HD_ + d];
      #pragma unroll
      for (int g=0; g<5; g++) acc[hh][g] = fmaf(qv, rv[g], acc[hh][g]);
    }
  }
  #pragma unroll
  for (int hh=0; hh<4; hh++){
    int h = hg + 4*hh;
    float* prow = P + ((size_t)bs*H_ + h)*NREL;
    #pragma unroll
    for (int g=0; g<4; g++) prow[jt + 64*g] = acc[hh][g];
    if (jt==0) prow[256] = acc[hh][4];
  }
}

// ---------------- softmax (+rna round: output feeds AV MMA) ----------------
__global__ void __launch_bounds__(256) softmax_kernel(float* __restrict__ Sc){
  size_t row = blockIdx.x;
  float* r = Sc + row*S_;
  int tid = threadIdx.x;
  float4 v = *(const float4*)(r + tid*4);
  float m = fmaxf(fmaxf(v.x,v.y), fmaxf(v.z,v.w));
  m = warp_max(m);
  __shared__ float sh[8];
  __shared__ float shm, shs;
  int w = tid>>5, lane = tid&31;
  if (lane==0) sh[w]=m;
  __syncthreads();
  if (tid==0){
    float M = sh[0];
    #pragma unroll
    for (int i=1;i<8;i++) M = fmaxf(M, sh[i]);
    shm = M;
  }
  __syncthreads();
  float M = shm;
  v.x = __expf(v.x-M); v.y = __expf(v.y-M); v.z = __expf(v.z-M); v.w = __expf(v.w-M);
  float s = v.x+v.y+v.z+v.w;
  s = warp_sum(s);
  if (lane==0) sh[w]=s;
  __syncthreads();
  if (tid==0){
    float SS=0.f;
    #pragma unroll
    for (int i=0;i<8;i++) SS += sh[i];
    shs = 1.f/SS;
  }
  __syncthreads();
  float inv = shs;
  v.x = tf32r(v.x*inv); v.y = tf32r(v.y*inv);
  v.z = tf32r(v.z*inv); v.w = tf32r(v.w*inv);
  *(float4*)(r + tid*4) = v;
}

// ---------------- launcher ----------------
#define GEMM_SMEM (6*ABYTES)            // 110592
#define SCORES_SMEM (2*128*68*4)        // 69632
#define AV_SMEM (3*PB_ + 3*VB_)         // 81408

extern "C" void kernel_launch(void* const* d_in, const int* in_sizes, int n_in,
                              void* d_out, int out_size)
{
  const float* x    = (const float*)d_in[0];
  const float* wq   = (const float*)d_in[1];
  const float* bq   = (const float*)d_in[2];
  const float* wk   = (const float*)d_in[3];
  const float* bk   = (const float*)d_in[4];
  const float* wv   = (const float*)d_in[5];
  const float* bv   = (const float*)d_in[6];
  const float* wo   = (const float*)d_in[7];
  const float* bo   = (const float*)d_in[8];
  const float* rel  = (const float*)d_in[9];
  const float* ln1g = (const float*)d_in[10];
  const float* ln1b = (const float*)d_in[11];
  const float* ln2g = (const float*)d_in[12];
  const float* ln2b = (const float*)d_in[13];
  const float* w1   = (const float*)d_in[14];
  const float* b1   = (const float*)d_in[15];
  const float* w2   = (const float*)d_in[16];
  const float* b2   = (const float*)d_in[17];
  float* out = (float*)d_out;

  float *h_, *q_, *k_, *v_, *relT_, *p_, *sc_, *o_, *x2_, *ff_;
  float *wqT_, *wkT_, *wvT_, *woT_, *w1T_, *w2T_;
  cudaGetSymbolAddress((void**)&h_,   g_h);
  cudaGetSymbolAddress((void**)&q_,   g_q);
  cudaGetSymbolAddress((void**)&k_,   g_k);
  cudaGetSymbolAddress((void**)&v_,   g_v);
  cudaGetSymbolAddress((void**)&relT_,g_relT);
  cudaGetSymbolAddress((void**)&p_,   g_p);
  cudaGetSymbolAddress((void**)&sc_,  g_sc);
  cudaGetSymbolAddress((void**)&o_,   g_o);
  cudaGetSymbolAddress((void**)&x2_,  g_x2);
  cudaGetSymbolAddress((void**)&ff_,  g_ff);
  cudaGetSymbolAddress((void**)&wqT_, g_wqT);
  cudaGetSymbolAddress((void**)&wkT_, g_wkT);
  cudaGetSymbolAddress((void**)&wvT_, g_wvT);
  cudaGetSymbolAddress((void**)&woT_, g_woT);
  cudaGetSymbolAddress((void**)&w1T_, g_w1T);
  cudaGetSymbolAddress((void**)&w2T_, g_w2T);

  static bool attr_done = false;
  if (!attr_done){
    cudaFuncSetAttribute(mma_gemm<EPI_BIAS,1>,       cudaFuncAttributeMaxDynamicSharedMemorySize, GEMM_SMEM);
    cudaFuncSetAttribute(mma_gemm<EPI_BIAS_RESID,0>, cudaFuncAttributeMaxDynamicSharedMemorySize, GEMM_SMEM);
    cudaFuncSetAttribute(mma_gemm<EPI_BIAS_GELU,1>,  cudaFuncAttributeMaxDynamicSharedMemorySize, GEMM_SMEM);
    cudaFuncSetAttribute(attn_scores_mma, cudaFuncAttributeMaxDynamicSharedMemorySize, SCORES_SMEM);
    cudaFuncSetAttribute(attn_av_mma,     cudaFuncAttributeMaxDynamicSharedMemorySize, AV_SMEM);
    attr_done = true;
  }

  // 0. weight transposes (+tf32 rounding)
  transpose_k<<<dim3(D_/32,   D_/32),  dim3(32,8)>>>(wq, wqT_, D_,   D_);
  transpose_k<<<dim3(D_/32,   D_/32),  dim3(32,8)>>>(wk, wkT_, D_,   D_);
  transpose_k<<<dim3(D_/32,   D_/32),  dim3(32,8)>>>(wv, wvT_, D_,   D_);
  transpose_k<<<dim3(D_/32,   D_/32),  dim3(32,8)>>>(wo, woT_, D_,   D_);
  transpose_k<<<dim3(4*D_/32, D_/32),  dim3(32,8)>>>(w1, w1T_, D_,   4*D_);
  transpose_k<<<dim3(D_/32,   4*D_/32),dim3(32,8)>>>(w2, w2T_, 4*D_, D_);

  // 1. LN1 (rounded output)
  ln_kernel<<<BS_, 256>>>(x, ln1g, ln1b, h_);
  // 2. Q/K/V projections (rounded outputs)
  mma_gemm<EPI_BIAS,1><<<dim3(8,32), 256, GEMM_SMEM>>>(h_, wqT_, bq, nullptr, q_, BS_, D_, D_);
  mma_gemm<EPI_BIAS,1><<<dim3(8,32), 256, GEMM_SMEM>>>(h_, wkT_, bk, nullptr, k_, BS_, D_, D_);
  mma_gemm<EPI_BIAS,1><<<dim3(8,32), 256, GEMM_SMEM>>>(h_, wvT_, bv, nullptr, v_, BS_, D_, D_);
  // 3. rel projection
  rel_transpose<<<(NREL*HD_ + 255)/256, 256>>>(rel, relT_);
  rel_proj<<<BS_, 256>>>(q_, relT_, p_);
  // 4. scores via mma + rel gather + scale
  attn_scores_mma<<<dim3(8,8,Bb_*H_), 256, SCORES_SMEM>>>(q_, k_, p_, sc_);
  // 5. softmax (rounded output)
  softmax_kernel<<<Bb_*H_*S_, 256>>>(sc_);
  // 6. attn @ V via mma (rounded output)
  attn_av_mma<<<dim3(8,Bb_*H_), 256, AV_SMEM>>>(sc_, v_, o_);
  // 7. output projection + residual
  mma_gemm<EPI_BIAS_RESID,0><<<dim3(8,32), 256, GEMM_SMEM>>>(o_, woT_, bo, x, x2_, BS_, D_, D_);
  // 8. LN2 (rounded output)
  ln_kernel<<<BS_, 256>>>(x2_, ln2g, ln2b, h_);
  // 9. FFN1 + exact GELU (rounded output)
  mma_gemm<EPI_BIAS_GELU,1><<<dim3(32,32), 256, GEMM_SMEM>>>(h_, w1T_, b1, nullptr, ff_, BS_, 4*D_, D_);
  // 10. FFN2 + residual -> out
  mma_gemm<EPI_BIAS_RESID,0><<<dim3(8,32), 256, GEMM_SMEM>>>(ff_, w2T_, b2, x2_, out, BS_, D_, 4*D_);
}

// round 6
// speedup vs baseline: 3.8904x; 1.8659x over previous
#include <cuda_runtime.h>
#include <cuda_fp16.h>
#include <math.h>
#include <stdint.h>

#define Bb_ 4
#define S_ 1024
#define D_ 1024
#define H_ 16
#define HD_ 64
#define R_ 128
#define NREL 257
#define BS_ (Bb_*S_)   // 4096
#define EPSLN 1e-5f

// -------- device scratch --------
__device__ __half g_h16[BS_*D_];
__device__ __half g_q16[BS_*D_];
__device__ __half g_k16[BS_*D_];
__device__ __half g_v16[BS_*D_];
__device__ __half g_o16[BS_*D_];
__device__ __half g_ff16[(size_t)BS_*4*D_];
__device__ float  g_relT[HD_*NREL];
__device__ float  g_p [ (size_t)BS_*H_*NREL ];
__device__ float  g_sc[ (size_t)Bb_*H_*S_*S_ ];   // fp32 scores
__device__ __half g_pr[ (size_t)Bb_*H_*S_*S_ ];   // fp16 probs
__device__ float  g_x2[BS_*D_];
__device__ __half g_wqT[D_*D_];
__device__ __half g_wkT[D_*D_];
__device__ __half g_wvT[D_*D_];
__device__ __half g_woT[D_*D_];
__device__ __half g_w1T[(size_t)D_*4*D_];
__device__ __half g_w2T[(size_t)4*D_*D_];

// ---------------- helpers ----------------
__device__ __forceinline__ float warp_sum(float v){
  #pragma unroll
  for (int o=16;o>0;o>>=1) v += __shfl_xor_sync(0xffffffffu, v, o);
  return v;
}
__device__ __forceinline__ float warp_max(float v){
  #pragma unroll
  for (int o=16;o>0;o>>=1) v = fmaxf(v, __shfl_xor_sync(0xffffffffu, v, o));
  return v;
}
__device__ __forceinline__ void mma_f16(float* d, const uint32_t* a, const uint32_t* b){
  asm volatile("mma.sync.aligned.m16n8k16.row.col.f32.f16.f16.f32 "
    "{%0,%1,%2,%3}, {%4,%5,%6,%7}, {%8,%9}, {%0,%1,%2,%3};"
    : "+f"(d[0]),"+f"(d[1]),"+f"(d[2]),"+f"(d[3])
    : "r"(a[0]),"r"(a[1]),"r"(a[2]),"r"(a[3]), "r"(b[0]),"r"(b[1]));
}
__device__ __forceinline__ void ldsm4(uint32_t& r0, uint32_t& r1, uint32_t& r2, uint32_t& r3,
                                      uint32_t addr){
  asm volatile("ldmatrix.sync.aligned.m8n8.x4.shared.b16 {%0,%1,%2,%3}, [%4];"
    : "=r"(r0),"=r"(r1),"=r"(r2),"=r"(r3) : "r"(addr));
}
__device__ __forceinline__ void ldsm4t(uint32_t& r0, uint32_t& r1, uint32_t& r2, uint32_t& r3,
                                       uint32_t addr){
  asm volatile("ldmatrix.sync.aligned.m8n8.x4.trans.shared.b16 {%0,%1,%2,%3}, [%4];"
    : "=r"(r0),"=r"(r1),"=r"(r2),"=r"(r3) : "r"(addr));
}
__device__ __forceinline__ void cp16(uint32_t dst, const void* src){
  asm volatile("cp.async.cg.shared.global [%0], [%1], 16;" :: "r"(dst), "l"(src));
}
#define CP_COMMIT() asm volatile("cp.async.commit_group;" ::: "memory")
#define CP_WAIT1()  asm volatile("cp.async.wait_group 1;" ::: "memory")
#define CP_WAIT0()  asm volatile("cp.async.wait_group 0;" ::: "memory")

#define EPI_BIAS        0
#define EPI_BIAS_RESID  1
#define EPI_BIAS_GELU   2
#define HST 40                      // padded halves per row for K32 tiles
#define HBYTES (128*HST*2)          // 10240

// ---------------- fp16 mma GEMM: C = A[M,K] @ Bt[N,K]^T (+epi) -------------
// 128x128x32 tile, 3-stage cp.async, 8 warps (4x2), warp 32x64
// OUT16=1 -> C is __half*, else float*
template<int EPI, int OUT16>
__global__ void __launch_bounds__(256) hgemm(const __half* __restrict__ A,
                                             const __half* __restrict__ Bt,
                                             const float* __restrict__ bias,
                                             const float* __restrict__ resid,
                                             void* __restrict__ Cv,
                                             int M, int N, int K)
{
  extern __shared__ char sm[];
  __half* Asm = (__half*)sm;
  __half* Bsm = (__half*)(sm + 3*HBYTES);
  const int tid = threadIdx.x;
  const int wid = tid >> 5, lane = tid & 31;
  const int warp_m = wid >> 1, warp_n = wid & 1;
  const int m0 = blockIdx.y*128, n0 = blockIdx.x*128;
  const int lr = lane >> 2, lc = lane & 3;
  const int grow = tid >> 1, gseg = (tid & 1)*16;

  const __half* Ag = A  + (size_t)(m0 + grow)*K + gseg;
  const __half* Bg = Bt + (size_t)(n0 + grow)*K + gseg;
  const uint32_t a_s = (uint32_t)__cvta_generic_to_shared(Asm) + (grow*HST + gseg)*2;
  const uint32_t b_s = (uint32_t)__cvta_generic_to_shared(Bsm) + (grow*HST + gseg)*2;

  // ldmatrix source addrs
  const uint32_t a_lm = (uint32_t)__cvta_generic_to_shared(Asm)
      + (((warp_m*32 + (lane & 15))*HST) + ((lane >> 4)*8))*2;
  const uint32_t b_lm = (uint32_t)__cvta_generic_to_shared(Bsm)
      + (((warp_n*64 + (lane & 7) + ((lane >> 4)&1)*8)*HST) + (((lane >> 3)&1)*8))*2;

  float acc[2][8][4];
  #pragma unroll
  for (int i=0;i<2;i++)
    #pragma unroll
    for (int j=0;j<8;j++)
      #pragma unroll
      for (int t=0;t<4;t++) acc[i][j][t]=0.f;

  const int NC = K >> 5;
  auto load = [&](int c, int s){
    const __half* ga = Ag + c*32;
    const __half* gb = Bg + c*32;
    const uint32_t da = a_s + s*HBYTES;
    const uint32_t db = b_s + s*HBYTES;
    cp16(da,      ga);
    cp16(da + 16, ga + 8);
    cp16(db,      gb);
    cp16(db + 16, gb + 8);
  };

  load(0,0); CP_COMMIT();
  if (NC > 1) load(1,1);
  CP_COMMIT();

  for (int c = 0; c < NC; c++){
    const int s = c - (c/3)*3;
    if (c + 1 < NC) CP_WAIT1(); else CP_WAIT0();
    __syncthreads();
    const uint32_t abase = a_lm + s*HBYTES;
    const uint32_t bbase = b_lm + s*HBYTES;
    #pragma unroll
    for (int ks=0; ks<2; ks++){
      uint32_t a[2][4], b[8][2];
      #pragma unroll
      for (int mf=0; mf<2; mf++)
        ldsm4(a[mf][0], a[mf][1], a[mf][2], a[mf][3],
              abase + (mf*16*HST + ks*16)*2);
      #pragma unroll
      for (int np=0; np<4; np++){
        uint32_t r0,r1,r2,r3;
        ldsm4(r0,r1,r2,r3, bbase + (np*16*HST + ks*16)*2);
        b[np*2+0][0]=r0; b[np*2+0][1]=r1;
        b[np*2+1][0]=r2; b[np*2+1][1]=r3;
      }
      #pragma unroll
      for (int mf=0; mf<2; mf++)
        #pragma unroll
        for (int nf=0; nf<8; nf++)
          mma_f16(acc[mf][nf], a[mf], b[nf]);
    }
    if (c + 2 < NC) load(c+2, (c+2) - ((c+2)/3)*3);
    CP_COMMIT();
    __syncthreads();
  }

  // epilogue
  #pragma unroll
  for (int mf=0; mf<2; mf++){
    #pragma unroll
    for (int half=0; half<2; half++){
      const int row = m0 + warp_m*32 + mf*16 + lr + half*8;
      const float* rrow = (EPI == EPI_BIAS_RESID) ? (resid + (size_t)row*N) : nullptr;
      #pragma unroll
      for (int nf=0; nf<8; nf++){
        const int col = n0 + warp_n*64 + nf*8 + 2*lc;
        float v0 = acc[mf][nf][half*2 + 0] + bias[col];
        float v1 = acc[mf][nf][half*2 + 1] + bias[col+1];
        if (EPI == EPI_BIAS_RESID){ v0 += rrow[col]; v1 += rrow[col+1]; }
        if (EPI == EPI_BIAS_GELU){
          v0 = 0.5f*v0*(1.0f + erff(v0*0.70710678118654752f));
          v1 = 0.5f*v1*(1.0f + erff(v1*0.70710678118654752f));
        }
        if (OUT16){
          __half2 hv = __floats2half2_rn(v0, v1);
          *(__half2*)((__half*)Cv + (size_t)row*N + col) = hv;
        } else {
          *(float2*)((float*)Cv + (size_t)row*N + col) = make_float2(v0, v1);
        }
      }
    }
  }
}

// ---------------- attention scores: Sc = (Q·K^T + relbias)*scale -----------
// grid (kt=8, qt=8, bh=64), CTA 128x128, K=64 one shot
#define QST 72
__global__ void __launch_bounds__(256) attn_scores_h(const __half* __restrict__ Q,
                                                     const __half* __restrict__ Km,
                                                     const float* __restrict__ P,
                                                     float* __restrict__ Sc)
{
  extern __shared__ char sm[];
  __half* Qs = (__half*)sm;                  // 128 x 72
  __half* Ks = (__half*)(sm + 128*QST*2);
  const int bh = blockIdx.z, b = bh >> 4, h = bh & 15;
  const int q0 = blockIdx.y*128, k0 = blockIdx.x*128;
  const int tid = threadIdx.x, wid = tid >> 5, lane = tid & 31;
  const int warp_m = wid >> 1, warp_n = wid & 1;
  const int lr = lane >> 2, lc = lane & 3;
  const size_t base = (size_t)b*S_*D_ + h*HD_;
  const int row = tid >> 1, seg = (tid & 1)*32;

  const __half* qp = Q  + base + (size_t)(q0 + row)*D_ + seg;
  const __half* kp = Km + base + (size_t)(k0 + row)*D_ + seg;
  #pragma unroll
  for (int i=0;i<4;i++){
    *(uint4*)&Qs[row*QST + seg + i*8] = *(const uint4*)(qp + i*8);
    *(uint4*)&Ks[row*QST + seg + i*8] = *(const uint4*)(kp + i*8);
  }
  __syncthreads();

  const uint32_t a_lm = (uint32_t)__cvta_generic_to_shared(Qs)
      + (((warp_m*32 + (lane & 15))*QST) + ((lane >> 4)*8))*2;
  const uint32_t b_lm = (uint32_t)__cvta_generic_to_shared(Ks)
      + (((warp_n*64 + (lane & 7) + ((lane >> 4)&1)*8)*QST) + (((lane >> 3)&1)*8))*2;

  float acc[2][8][4];
  #pragma unroll
  for (int i=0;i<2;i++)
    #pragma unroll
    for (int j=0;j<8;j++)
      #pragma unroll
      for (int t=0;t<4;t++) acc[i][j][t]=0.f;

  #pragma unroll
  for (int ks=0; ks<4; ks++){
    uint32_t a[2][4], b[8][2];
    #pragma unroll
    for (int mf=0; mf<2; mf++)
      ldsm4(a[mf][0], a[mf][1], a[mf][2], a[mf][3],
            a_lm + (mf*16*QST + ks*16)*2);
    #pragma unroll
    for (int np=0; np<4; np++){
      uint32_t r0,r1,r2,r3;
      ldsm4(r0,r1,r2,r3, b_lm + (np*16*QST + ks*16)*2);
      b[np*2+0][0]=r0; b[np*2+0][1]=r1;
      b[np*2+1][0]=r2; b[np*2+1][1]=r3;
    }
    #pragma unroll
    for (int mf=0; mf<2; mf++)
      #pragma unroll
      for (int nf=0; nf<8; nf++)
        mma_f16(acc[mf][nf], a[mf], b[nf]);
  }

  const float scale = 0.125f;
  #pragma unroll
  for (int mf=0; mf<2; mf++){
    #pragma unroll
    for (int hf=0; hf<2; hf++){
      const int q = q0 + warp_m*32 + mf*16 + hf*8 + lr;
      const float* prow = P + ((size_t)(b*S_ + q)*H_ + h)*NREL;
      float* srow = Sc + ((size_t)bh*S_ + q)*S_;
      #pragma unroll
      for (int nf=0; nf<8; nf++){
        const int col = k0 + warp_n*64 + nf*8 + 2*lc;
        int i0 = col - q;     i0 = i0 < -R_ ? -R_ : (i0 > R_ ? R_ : i0);
        int i1 = col + 1 - q; i1 = i1 < -R_ ? -R_ : (i1 > R_ ? R_ : i1);
        float v0 = (acc[mf][nf][hf*2 + 0] + prow[i0 + R_]) * scale;
        float v1 = (acc[mf][nf][hf*2 + 1] + prow[i1 + R_]) * scale;
        *(float2*)(srow + col) = make_float2(v0, v1);
      }
    }
  }
}

// ---------------- attn @ V: O[128,64] = Pr[128,1024] @ V[1024,64] ----------
#define VST 72
#define PBYT (128*HST*2)    // 10240
#define VBYT (32*VST*2)     // 4608
__global__ void __launch_bounds__(256) attn_av_h(const __half* __restrict__ Pr,
                                                 const __half* __restrict__ V,
                                                 __half* __restrict__ O)
{
  extern __shared__ char sm[];
  __half* Ps = (__half*)sm;               // 3 stages 128x40
  __half* Vs = (__half*)(sm + 3*PBYT);    // 3 stages 32x72
  const int bh = blockIdx.y, b = bh >> 4, h = bh & 15;
  const int q0 = blockIdx.x*128;
  const int tid = threadIdx.x, wid = tid >> 5, lane = tid & 31;
  const int lr = lane >> 2, lc = lane & 3;
  const __half* Pb = Pr + ((size_t)bh*S_ + q0)*S_;
  const size_t vbase = (size_t)b*S_*D_ + h*HD_;

  const int prow = tid >> 1, pseg = (tid & 1)*16;
  const int vrow = tid >> 3, vcol = (tid & 7)*8;
  const uint32_t p_s = (uint32_t)__cvta_generic_to_shared(Ps) + (prow*HST + pseg)*2;
  const uint32_t v_s = (uint32_t)__cvta_generic_to_shared(Vs) + (vrow*VST + vcol)*2;

  // A frag: warp tile 16 rows
  const uint32_t a_lm = (uint32_t)__cvta_generic_to_shared(Ps)
      + (((wid*16 + (lane & 15))*HST) + ((lane >> 4)*8))*2;
  // B frag (trans): krow = (lane&7) + ((lane>>3)&1)*8 ; col offset ((lane>>4)&1)*8
  const uint32_t b_lm = (uint32_t)__cvta_generic_to_shared(Vs)
      + ((((lane & 7) + ((lane >> 3)&1)*8)*VST) + (((lane >> 4)&1)*8))*2;

  float acc[8][4];
  #pragma unroll
  for (int j=0;j<8;j++)
    #pragma unroll
    for (int t=0;t<4;t++) acc[j][t]=0.f;

  auto load = [&](int c, int s){
    const __half* gp = Pb + (size_t)prow*S_ + c*32 + pseg;
    cp16(p_s + s*PBYT,      gp);
    cp16(p_s + s*PBYT + 16, gp + 8);     // FIX: second 8 halves of this thread's 16-half segment
    const __half* gv = V + vbase + (size_t)(c*32 + vrow)*D_ + vcol;
    cp16(v_s + s*VBYT, gv);
  };

  const int NC = S_ >> 5;  // 32
  load(0,0); CP_COMMIT();
  load(1,1); CP_COMMIT();

  for (int c = 0; c < NC; c++){
    const int s = c - (c/3)*3;
    if (c + 1 < NC) CP_WAIT1(); else CP_WAIT0();
    __syncthreads();
    const uint32_t abase = a_lm + s*PBYT;
    const uint32_t bbase = b_lm + s*VBYT;
    #pragma unroll
    for (int ks=0; ks<2; ks++){
      uint32_t a[4], b[8][2];
      ldsm4(a[0], a[1], a[2], a[3], abase + (ks*16)*2);
      #pragma unroll
      for (int np=0; np<4; np++){
        uint32_t r0,r1,r2,r3;
        ldsm4t(r0,r1,r2,r3, bbase + (ks*16*VST + np*16)*2);
        b[np*2+0][0]=r0; b[np*2+0][1]=r1;
        b[np*2+1][0]=r2; b[np*2+1][1]=r3;
      }
      #pragma unroll
      for (int nf=0; nf<8; nf++)
        mma_f16(acc[nf], a, b[nf]);
    }
    if (c + 2 < NC) load(c+2, (c+2) - ((c+2)/3)*3);
    CP_COMMIT();
    __syncthreads();
  }

  #pragma unroll
  for (int hf=0; hf<2; hf++){
    const int q = q0 + wid*16 + hf*8 + lr;
    __half* orow = O + vbase + (size_t)q*D_;
    #pragma unroll
    for (int nf=0; nf<8; nf++){
      const int col = nf*8 + 2*lc;
      *(__half2*)(orow + col) = __floats2half2_rn(acc[nf][hf*2+0], acc[nf][hf*2+1]);
    }
  }
}

// ---------------- weight transpose fp32 -> fp16 [N,K] ----------------
__global__ void __launch_bounds__(256) transpose_k_h(const float* __restrict__ W,
                                                     __half* __restrict__ Wt,
                                                     int Kd, int Nd)
{
  __shared__ float t[32][33];
  int n = blockIdx.x*32 + threadIdx.x;
  int k = blockIdx.y*32 + threadIdx.y;
  #pragma unroll
  for (int i=0;i<32;i+=8)
    t[threadIdx.y+i][threadIdx.x] = W[(size_t)(k+i)*Nd + n];
  __syncthreads();
  int n2 = blockIdx.x*32 + threadIdx.y;
  int k2 = blockIdx.y*32 + threadIdx.x;
  #pragma unroll
  for (int i=0;i<32;i+=8)
    Wt[(size_t)(n2+i)*Kd + k2] = __float2half_rn(t[threadIdx.x][threadIdx.y+i]);
}

// ---------------- LayerNorm fp32 in -> fp16 out ----------------
__global__ void __launch_bounds__(256) ln_kernel_h(const float* __restrict__ x,
                                                   const float* __restrict__ g,
                                                   const float* __restrict__ bta,
                                                   __half* __restrict__ y)
{
  int row = blockIdx.x;
  int tid = threadIdx.x;
  const float* xr = x + (size_t)row*D_;
  float4 v = *(const float4*)(xr + tid*4);
  float s  = v.x+v.y+v.z+v.w;
  float ss = v.x*v.x+v.y*v.y+v.z*v.z+v.w*v.w;
  s = warp_sum(s); ss = warp_sum(ss);
  __shared__ float sh[16];
  __shared__ float sh_mu, sh_rs;
  int w = tid>>5, lane = tid&31;
  if (lane==0){ sh[w]=s; sh[8+w]=ss; }
  __syncthreads();
  if (tid==0){
    float S=0.f, SS=0.f;
    #pragma unroll
    for (int i=0;i<8;i++){ S+=sh[i]; SS+=sh[8+i]; }
    float mu  = S*(1.f/(float)D_);
    float var = SS*(1.f/(float)D_) - mu*mu;
    sh_mu = mu; sh_rs = rsqrtf(var + EPSLN);
  }
  __syncthreads();
  float mu = sh_mu, rs = sh_rs;
  float4 gv = *(const float4*)(g   + tid*4);
  float4 bv = *(const float4*)(bta + tid*4);
  __half2 h0 = __floats2half2_rn((v.x-mu)*rs*gv.x + bv.x, (v.y-mu)*rs*gv.y + bv.y);
  __half2 h1 = __floats2half2_rn((v.z-mu)*rs*gv.z + bv.z, (v.w-mu)*rs*gv.w + bv.w);
  uint2 pk; pk.x = *(uint32_t*)&h0; pk.y = *(uint32_t*)&h1;
  *(uint2*)(y + (size_t)row*D_ + tid*4) = pk;
}

// ---------------- rel_embed transpose ----------------
__global__ void rel_transpose(const float* __restrict__ rel, float* __restrict__ relT){
  int i = blockIdx.x*256 + threadIdx.x;
  if (i < NREL*HD_){
    int j = i / HD_, d = i % HD_;
    relT[d*NREL + j] = rel[i];
  }
}

// ---------------- rel projection (reads fp16 Q) ----------------
__global__ void __launch_bounds__(256) rel_proj(const __half* __restrict__ Q,
                                                const float* __restrict__ relT,
                                                float* __restrict__ P)
{
  int bs = blockIdx.x;
  __shared__ float sq[D_];
  int tid = threadIdx.x;
  {
    uint2 raw = *(const uint2*)(Q + (size_t)bs*D_ + tid*4);
    __half2 h0 = *reinterpret_cast<__half2*>(&raw.x);
    __half2 h1 = *reinterpret_cast<__half2*>(&raw.y);
    sq[tid*4+0] = __low2float(h0); sq[tid*4+1] = __high2float(h0);
    sq[tid*4+2] = __low2float(h1); sq[tid*4+3] = __high2float(h1);
  }
  __syncthreads();

  int hg = tid >> 6;
  int jt = tid & 63;
  float acc[4][5];
  #pragma unroll
  for (int a=0;a<4;a++)
    #pragma unroll
    for (int g=0;g<5;g++) acc[a][g]=0.f;

  for (int d=0; d<HD_; d++){
    const float* rrow = relT + d*NREL;
    float rv[5];
    #pragma unroll
    for (int g=0; g<4; g++) rv[g] = __ldg(rrow + jt + 64*g);
    rv[4] = (jt==0) ? __ldg(rrow + 256) : 0.f;
    #pragma unroll
    for (int hh=0; hh<4; hh++){
      float qv = sq[(hg + 4*hh)*HD_ + d];
      #pragma unroll
      for (int g=0; g<5; g++) acc[hh][g] = fmaf(qv, rv[g], acc[hh][g]);
    }
  }
  #pragma unroll
  for (int hh=0; hh<4; hh++){
    int h = hg + 4*hh;
    float* prow = P + ((size_t)bs*H_ + h)*NREL;
    #pragma unroll
    for (int g=0; g<4; g++) prow[jt + 64*g] = acc[hh][g];
    if (jt==0) prow[256] = acc[hh][4];
  }
}

// ---------------- softmax: fp32 in, fp16 out ----------------
__global__ void __launch_bounds__(256) softmax_h(const float* __restrict__ Sc,
                                                 __half* __restrict__ Pr){
  size_t row = blockIdx.x;
  const float* r = Sc + row*S_;
  int tid = threadIdx.x;
  float4 v = *(const float4*)(r + tid*4);
  float m = fmaxf(fmaxf(v.x,v.y), fmaxf(v.z,v.w));
  m = warp_max(m);
  __shared__ float sh[8];
  __shared__ float shm, shs;
  int w = tid>>5, lane = tid&31;
  if (lane==0) sh[w]=m;
  __syncthreads();
  if (tid==0){
    float M = sh[0];
    #pragma unroll
    for (int i=1;i<8;i++) M = fmaxf(M, sh[i]);
    shm = M;
  }
  __syncthreads();
  float M = shm;
  v.x = __expf(v.x-M); v.y = __expf(v.y-M); v.z = __expf(v.z-M); v.w = __expf(v.w-M);
  float s = v.x+v.y+v.z+v.w;
  s = warp_sum(s);
  if (lane==0) sh[w]=s;
  __syncthreads();
  if (tid==0){
    float SS=0.f;
    #pragma unroll
    for (int i=0;i<8;i++) SS += sh[i];
    shs = 1.f/SS;
  }
  __syncthreads();
  float inv = shs;
  __half2 h0 = __floats2half2_rn(v.x*inv, v.y*inv);
  __half2 h1 = __floats2half2_rn(v.z*inv, v.w*inv);
  uint2 pk; pk.x = *(uint32_t*)&h0; pk.y = *(uint32_t*)&h1;
  *(uint2*)(Pr + row*S_ + tid*4) = pk;
}

// ---------------- launcher ----------------
#define GEMM_SMEM   (6*HBYTES)           // 61440
#define SCORES_SMEM (2*128*QST*2)        // 36864
#define AV_SMEM     (3*PBYT + 3*VBYT)    // 44544

extern "C" void kernel_launch(void* const* d_in, const int* in_sizes, int n_in,
                              void* d_out, int out_size)
{
  const float* x    = (const float*)d_in[0];
  const float* wq   = (const float*)d_in[1];
  const float* bq   = (const float*)d_in[2];
  const float* wk   = (const float*)d_in[3];
  const float* bk   = (const float*)d_in[4];
  const float* wv   = (const float*)d_in[5];
  const float* bv   = (const float*)d_in[6];
  const float* wo   = (const float*)d_in[7];
  const float* bo   = (const float*)d_in[8];
  const float* rel  = (const float*)d_in[9];
  const float* ln1g = (const float*)d_in[10];
  const float* ln1b = (const float*)d_in[11];
  const float* ln2g = (const float*)d_in[12];
  const float* ln2b = (const float*)d_in[13];
  const float* w1   = (const float*)d_in[14];
  const float* b1   = (const float*)d_in[15];
  const float* w2   = (const float*)d_in[16];
  const float* b2   = (const float*)d_in[17];
  float* out = (float*)d_out;

  __half *h16_, *q16_, *k16_, *v16_, *o16_, *ff16_, *pr_;
  __half *wqT_, *wkT_, *wvT_, *woT_, *w1T_, *w2T_;
  float *relT_, *p_, *sc_, *x2_;
  cudaGetSymbolAddress((void**)&h16_, g_h16);
  cudaGetSymbolAddress((void**)&q16_, g_q16);
  cudaGetSymbolAddress((void**)&k16_, g_k16);
  cudaGetSymbolAddress((void**)&v16_, g_v16);
  cudaGetSymbolAddress((void**)&o16_, g_o16);
  cudaGetSymbolAddress((void**)&ff16_,g_ff16);
  cudaGetSymbolAddress((void**)&pr_,  g_pr);
  cudaGetSymbolAddress((void**)&relT_,g_relT);
  cudaGetSymbolAddress((void**)&p_,   g_p);
  cudaGetSymbolAddress((void**)&sc_,  g_sc);
  cudaGetSymbolAddress((void**)&x2_,  g_x2);
  cudaGetSymbolAddress((void**)&wqT_, g_wqT);
  cudaGetSymbolAddress((void**)&wkT_, g_wkT);
  cudaGetSymbolAddress((void**)&wvT_, g_wvT);
  cudaGetSymbolAddress((void**)&woT_, g_woT);
  cudaGetSymbolAddress((void**)&w1T_, g_w1T);
  cudaGetSymbolAddress((void**)&w2T_, g_w2T);

  static bool attr_done = false;
  if (!attr_done){
    cudaFuncSetAttribute(hgemm<EPI_BIAS,1>,       cudaFuncAttributeMaxDynamicSharedMemorySize, GEMM_SMEM);
    cudaFuncSetAttribute(hgemm<EPI_BIAS_RESID,0>, cudaFuncAttributeMaxDynamicSharedMemorySize, GEMM_SMEM);
    cudaFuncSetAttribute(hgemm<EPI_BIAS_GELU,1>,  cudaFuncAttributeMaxDynamicSharedMemorySize, GEMM_SMEM);
    cudaFuncSetAttribute(attn_scores_h, cudaFuncAttributeMaxDynamicSharedMemorySize, SCORES_SMEM);
    cudaFuncSetAttribute(attn_av_h,     cudaFuncAttributeMaxDynamicSharedMemorySize, AV_SMEM);
    attr_done = true;
  }

  // 0. weight transposes -> fp16 [N,K]
  transpose_k_h<<<dim3(D_/32,   D_/32),  dim3(32,8)>>>(wq, wqT_, D_,   D_);
  transpose_k_h<<<dim3(D_/32,   D_/32),  dim3(32,8)>>>(wk, wkT_, D_,   D_);
  transpose_k_h<<<dim3(D_/32,   D_/32),  dim3(32,8)>>>(wv, wvT_, D_,   D_);
  transpose_k_h<<<dim3(D_/32,   D_/32),  dim3(32,8)>>>(wo, woT_, D_,   D_);
  transpose_k_h<<<dim3(4*D_/32, D_/32),  dim3(32,8)>>>(w1, w1T_, D_,   4*D_);
  transpose_k_h<<<dim3(D_/32,   4*D_/32),dim3(32,8)>>>(w2, w2T_, 4*D_, D_);

  // 1. LN1 -> fp16
  ln_kernel_h<<<BS_, 256>>>(x, ln1g, ln1b, h16_);
  // 2. Q/K/V projections (fp16 out)
  hgemm<EPI_BIAS,1><<<dim3(8,32), 256, GEMM_SMEM>>>(h16_, wqT_, bq, nullptr, q16_, BS_, D_, D_);
  hgemm<EPI_BIAS,1><<<dim3(8,32), 256, GEMM_SMEM>>>(h16_, wkT_, bk, nullptr, k16_, BS_, D_, D_);
  hgemm<EPI_BIAS,1><<<dim3(8,32), 256, GEMM_SMEM>>>(h16_, wvT_, bv, nullptr, v16_, BS_, D_, D_);
  // 3. rel projection
  rel_transpose<<<(NREL*HD_ + 255)/256, 256>>>(rel, relT_);
  rel_proj<<<BS_, 256>>>(q16_, relT_, p_);
  // 4. scores + rel gather + scale (fp32 out)
  attn_scores_h<<<dim3(8,8,Bb_*H_), 256, SCORES_SMEM>>>(q16_, k16_, p_, sc_);
  // 5. softmax -> fp16 probs
  softmax_h<<<Bb_*H_*S_, 256>>>(sc_, pr_);
  // 6. attn @ V -> fp16
  attn_av_h<<<dim3(8,Bb_*H_), 256, AV_SMEM>>>(pr_, v16_, o16_);
  // 7. output projection + residual (fp32 out)
  hgemm<EPI_BIAS_RESID,0><<<dim3(8,32), 256, GEMM_SMEM>>>(o16_, woT_, bo, x, x2_, BS_, D_, D_);
  // 8. LN2 -> fp16
  ln_kernel_h<<<BS_, 256>>>(x2_, ln2g, ln2b, h16_);
  // 9. FFN1 + exact GELU (fp16 out)
  hgemm<EPI_BIAS_GELU,1><<<dim3(32,32), 256, GEMM_SMEM>>>(h16_, w1T_, b1, nullptr, ff16_, BS_, 4*D_, D_);
  // 10. FFN2 + residual -> out (fp32)
  hgemm<EPI_BIAS_RESID,0><<<dim3(8,32), 256, GEMM_SMEM>>>(ff16_, w2T_, b2, x2_, out, BS_, D_, 4*D_);
}

// round 7
// speedup vs baseline: 4.5577x; 1.1715x over previous
#include <cuda_runtime.h>
#include <cuda_fp16.h>
#include <math.h>
#include <stdint.h>

#define Bb_ 4
#define S_ 1024
#define D_ 1024
#define H_ 16
#define HD_ 64
#define R_ 128
#define NREL 257
#define BS_ (Bb_*S_)   // 4096
#define EPSLN 1e-5f

// -------- device scratch --------
__device__ __half g_h16[BS_*D_];
__device__ __half g_q16[BS_*D_];
__device__ __half g_k16[BS_*D_];
__device__ __half g_v16[BS_*D_];
__device__ __half g_o16[BS_*D_];
__device__ __half g_ff16[(size_t)BS_*4*D_];
__device__ float  g_relT[HD_*NREL];
__device__ float  g_p [ (size_t)BS_*H_*NREL ];    // pre-scaled rel projection
__device__ float  g_x2[BS_*D_];
__device__ __half g_wqT[D_*D_];
__device__ __half g_wkT[D_*D_];
__device__ __half g_wvT[D_*D_];
__device__ __half g_woT[D_*D_];
__device__ __half g_w1T[(size_t)D_*4*D_];
__device__ __half g_w2T[(size_t)4*D_*D_];

// ---------------- helpers ----------------
__device__ __forceinline__ float warp_sum(float v){
  #pragma unroll
  for (int o=16;o>0;o>>=1) v += __shfl_xor_sync(0xffffffffu, v, o);
  return v;
}
__device__ __forceinline__ float warp_max(float v){
  #pragma unroll
  for (int o=16;o>0;o>>=1) v = fmaxf(v, __shfl_xor_sync(0xffffffffu, v, o));
  return v;
}
__device__ __forceinline__ void mma_f16(float* d, const uint32_t* a, const uint32_t* b){
  asm volatile("mma.sync.aligned.m16n8k16.row.col.f32.f16.f16.f32 "
    "{%0,%1,%2,%3}, {%4,%5,%6,%7}, {%8,%9}, {%0,%1,%2,%3};"
    : "+f"(d[0]),"+f"(d[1]),"+f"(d[2]),"+f"(d[3])
    : "r"(a[0]),"r"(a[1]),"r"(a[2]),"r"(a[3]), "r"(b[0]),"r"(b[1]));
}
__device__ __forceinline__ void ldsm4(uint32_t& r0, uint32_t& r1, uint32_t& r2, uint32_t& r3,
                                      uint32_t addr){
  asm volatile("ldmatrix.sync.aligned.m8n8.x4.shared.b16 {%0,%1,%2,%3}, [%4];"
    : "=r"(r0),"=r"(r1),"=r"(r2),"=r"(r3) : "r"(addr));
}
__device__ __forceinline__ void ldsm4t(uint32_t& r0, uint32_t& r1, uint32_t& r2, uint32_t& r3,
                                       uint32_t addr){
  asm volatile("ldmatrix.sync.aligned.m8n8.x4.trans.shared.b16 {%0,%1,%2,%3}, [%4];"
    : "=r"(r0),"=r"(r1),"=r"(r2),"=r"(r3) : "r"(addr));
}
__device__ __forceinline__ void cp16(uint32_t dst, const void* src){
  asm volatile("cp.async.cg.shared.global [%0], [%1], 16;" :: "r"(dst), "l"(src));
}
#define CP_COMMIT() asm volatile("cp.async.commit_group;" ::: "memory")
#define CP_WAIT1()  asm volatile("cp.async.wait_group 1;" ::: "memory")
#define CP_WAIT0()  asm volatile("cp.async.wait_group 0;" ::: "memory")
#define CP_WAIT2()  asm volatile("cp.async.wait_group 2;" ::: "memory")

#define EPI_BIAS        0
#define EPI_BIAS_RESID  1
#define EPI_BIAS_GELU   2
#define HST 40                      // padded halves per row for K32 tiles
#define HBYTES (128*HST*2)          // 10240

// ---------------- fp16 mma GEMM: C = A[M,K] @ Bt[N,K]^T (+epi) -------------
template<int EPI, int OUT16>
__global__ void __launch_bounds__(256) hgemm(const __half* __restrict__ A,
                                             const __half* __restrict__ Bt,
                                             const float* __restrict__ bias,
                                             const float* __restrict__ resid,
                                             void* __restrict__ Cv,
                                             int M, int N, int K)
{
  extern __shared__ char sm[];
  __half* Asm = (__half*)sm;
  __half* Bsm = (__half*)(sm + 3*HBYTES);
  const int tid = threadIdx.x;
  const int wid = tid >> 5, lane = tid & 31;
  const int warp_m = wid >> 1, warp_n = wid & 1;
  const int m0 = blockIdx.y*128, n0 = blockIdx.x*128;
  const int lr = lane >> 2, lc = lane & 3;
  const int grow = tid >> 1, gseg = (tid & 1)*16;

  const __half* Ag = A  + (size_t)(m0 + grow)*K + gseg;
  const __half* Bg = Bt + (size_t)(n0 + grow)*K + gseg;
  const uint32_t a_s = (uint32_t)__cvta_generic_to_shared(Asm) + (grow*HST + gseg)*2;
  const uint32_t b_s = (uint32_t)__cvta_generic_to_shared(Bsm) + (grow*HST + gseg)*2;

  const uint32_t a_lm = (uint32_t)__cvta_generic_to_shared(Asm)
      + (((warp_m*32 + (lane & 15))*HST) + ((lane >> 4)*8))*2;
  const uint32_t b_lm = (uint32_t)__cvta_generic_to_shared(Bsm)
      + (((warp_n*64 + (lane & 7) + ((lane >> 4)&1)*8)*HST) + (((lane >> 3)&1)*8))*2;

  float acc[2][8][4];
  #pragma unroll
  for (int i=0;i<2;i++)
    #pragma unroll
    for (int j=0;j<8;j++)
      #pragma unroll
      for (int t=0;t<4;t++) acc[i][j][t]=0.f;

  const int NC = K >> 5;
  auto load = [&](int c, int s){
    const __half* ga = Ag + c*32;
    const __half* gb = Bg + c*32;
    const uint32_t da = a_s + s*HBYTES;
    const uint32_t db = b_s + s*HBYTES;
    cp16(da,      ga);
    cp16(da + 16, ga + 8);
    cp16(db,      gb);
    cp16(db + 16, gb + 8);
  };

  load(0,0); CP_COMMIT();
  if (NC > 1) load(1,1);
  CP_COMMIT();

  for (int c = 0; c < NC; c++){
    const int s = c - (c/3)*3;
    if (c + 1 < NC) CP_WAIT1(); else CP_WAIT0();
    __syncthreads();
    const uint32_t abase = a_lm + s*HBYTES;
    const uint32_t bbase = b_lm + s*HBYTES;
    #pragma unroll
    for (int ks=0; ks<2; ks++){
      uint32_t a[2][4], b[8][2];
      #pragma unroll
      for (int mf=0; mf<2; mf++)
        ldsm4(a[mf][0], a[mf][1], a[mf][2], a[mf][3],
              abase + (mf*16*HST + ks*16)*2);
      #pragma unroll
      for (int np=0; np<4; np++){
        uint32_t r0,r1,r2,r3;
        ldsm4(r0,r1,r2,r3, bbase + (np*16*HST + ks*16)*2);
        b[np*2+0][0]=r0; b[np*2+0][1]=r1;
        b[np*2+1][0]=r2; b[np*2+1][1]=r3;
      }
      #pragma unroll
      for (int mf=0; mf<2; mf++)
        #pragma unroll
        for (int nf=0; nf<8; nf++)
          mma_f16(acc[mf][nf], a[mf], b[nf]);
    }
    if (c + 2 < NC) load(c+2, (c+2) - ((c+2)/3)*3);
    CP_COMMIT();
    __syncthreads();
  }

  #pragma unroll
  for (int mf=0; mf<2; mf++){
    #pragma unroll
    for (int half=0; half<2; half++){
      const int row = m0 + warp_m*32 + mf*16 + lr + half*8;
      const float* rrow = (EPI == EPI_BIAS_RESID) ? (resid + (size_t)row*N) : nullptr;
      #pragma unroll
      for (int nf=0; nf<8; nf++){
        const int col = n0 + warp_n*64 + nf*8 + 2*lc;
        float v0 = acc[mf][nf][half*2 + 0] + bias[col];
        float v1 = acc[mf][nf][half*2 + 1] + bias[col+1];
        if (EPI == EPI_BIAS_RESID){ v0 += rrow[col]; v1 += rrow[col+1]; }
        if (EPI == EPI_BIAS_GELU){
          v0 = 0.5f*v0*(1.0f + erff(v0*0.70710678118654752f));
          v1 = 0.5f*v1*(1.0f + erff(v1*0.70710678118654752f));
        }
        if (OUT16){
          __half2 hv = __floats2half2_rn(v0, v1);
          *(__half2*)((__half*)Cv + (size_t)row*N + col) = hv;
        } else {
          *(float2*)((float*)Cv + (size_t)row*N + col) = make_float2(v0, v1);
        }
      }
    }
  }
}

// ---------------- fused flash attention --------------------------------
// grid (8 q-tiles, 64 bh), 256 thr. Per warp: 16 q-rows. 8 K/V tiles of 128.
#define FST 72
#define FTILE_B (128*FST*2)   // 18432
#define FLASH_SMEM (7*FTILE_B) // Q + 3 stages x (K+V) = 129024
__global__ void __launch_bounds__(256) flash_attn(const __half* __restrict__ Q,
                                                  const __half* __restrict__ Km,
                                                  const __half* __restrict__ Vm,
                                                  const float* __restrict__ P,
                                                  __half* __restrict__ O)
{
  extern __shared__ char sm[];
  const int bh = blockIdx.y, b = bh >> 4, h = bh & 15;
  const int q0 = blockIdx.x*128;
  const int tid = threadIdx.x, wid = tid >> 5, lane = tid & 31;
  const int lr = lane >> 2, lc = lane & 3;
  const size_t base = (size_t)b*S_*D_ + h*HD_;
  const uint32_t smb = (uint32_t)__cvta_generic_to_shared(sm);

  const int grow = tid >> 1, gseg = (tid & 1)*32;
  {
    const __half* qg = Q + base + (size_t)(q0 + grow)*D_ + gseg;
    uint32_t dst = smb + (grow*FST + gseg)*2;
    cp16(dst,    qg);     cp16(dst+16, qg+8);
    cp16(dst+32, qg+16);  cp16(dst+48, qg+24);
  }
  CP_COMMIT();
  auto load_kv = [&](int c, int s){
    const __half* kg = Km + base + (size_t)(c*128 + grow)*D_ + gseg;
    const __half* vg = Vm + base + (size_t)(c*128 + grow)*D_ + gseg;
    uint32_t kd = smb + FTILE_B + s*(2*FTILE_B) + (grow*FST + gseg)*2;
    uint32_t vd = kd + FTILE_B;
    cp16(kd,    kg);     cp16(kd+16, kg+8);
    cp16(kd+32, kg+16);  cp16(kd+48, kg+24);
    cp16(vd,    vg);     cp16(vd+16, vg+8);
    cp16(vd+32, vg+16);  cp16(vd+48, vg+24);
  };
  load_kv(0,0); CP_COMMIT();
  load_kv(1,1); CP_COMMIT();

  CP_WAIT2();          // Q done
  __syncthreads();

  // Q fragments, pre-scaled by 0.125 (exact)
  uint32_t a_q[4][4];
  {
    const uint32_t a_lm = smb + (((wid*16 + (lane & 15))*FST) + ((lane >> 4)*8))*2;
    const __half2 sc8 = __half2half2(__float2half(0.125f));
    #pragma unroll
    for (int ks=0; ks<4; ks++){
      ldsm4(a_q[ks][0], a_q[ks][1], a_q[ks][2], a_q[ks][3], a_lm + (ks*16)*2);
      #pragma unroll
      for (int r=0;r<4;r++){
        __half2 hv = *reinterpret_cast<__half2*>(&a_q[ks][r]);
        hv = __hmul2(hv, sc8);
        a_q[ks][r] = *reinterpret_cast<uint32_t*>(&hv);
      }
    }
  }

  const int qrow0 = q0 + wid*16 + lr;
  const float* prow0 = P + ((size_t)(b*S_ + qrow0)*H_ + h)*NREL + R_;
  const float* prow1 = prow0 + (size_t)8*H_*NREL;

  float m0 = -1e30f, m1 = -1e30f, l0 = 0.f, l1 = 0.f;
  float acc_o[8][4];
  #pragma unroll
  for (int j=0;j<8;j++)
    #pragma unroll
    for (int t=0;t<4;t++) acc_o[j][t] = 0.f;

  for (int kt = 0; kt < 8; kt++){
    const int s = kt - (kt/3)*3;
    CP_WAIT1();
    __syncthreads();
    const uint32_t kbase = smb + FTILE_B + s*(2*FTILE_B);
    const uint32_t vbase = kbase + FTILE_B;

    // ---- S = (Q/8) K^T  (128 keys, d=64) ----
    float accs[16][4];
    #pragma unroll
    for (int j=0;j<16;j++)
      #pragma unroll
      for (int t=0;t<4;t++) accs[j][t] = 0.f;

    const uint32_t bk_lm = kbase
        + ((((lane & 7) + ((lane >> 4)&1)*8)*FST) + (((lane >> 3)&1)*8))*2;
    #pragma unroll
    for (int ks=0; ks<4; ks++){
      uint32_t bfr[16][2];
      #pragma unroll
      for (int np=0; np<8; np++){
        uint32_t r0,r1,r2,r3;
        ldsm4(r0,r1,r2,r3, bk_lm + (np*16*FST + ks*16)*2);
        bfr[np*2+0][0]=r0; bfr[np*2+0][1]=r1;
        bfr[np*2+1][0]=r2; bfr[np*2+1][1]=r3;
      }
      #pragma unroll
      for (int nf=0; nf<16; nf++)
        mma_f16(accs[nf], a_q[ks], bfr[nf]);
    }

    // ---- + rel bias (pre-scaled P) ----
    const int cq0 = kt*128 + 2*lc - qrow0;
    #pragma unroll
    for (int nf=0; nf<16; nf++){
      int c0 = cq0 + nf*8;
      int i00 = c0;     i00 = i00 < -R_ ? -R_ : (i00 > R_ ? R_ : i00);
      int i01 = c0 + 1; i01 = i01 < -R_ ? -R_ : (i01 > R_ ? R_ : i01);
      int i10 = c0 - 8; i10 = i10 < -R_ ? -R_ : (i10 > R_ ? R_ : i10);
      int i11 = c0 - 7; i11 = i11 < -R_ ? -R_ : (i11 > R_ ? R_ : i11);
      accs[nf][0] += __ldg(prow0 + i00);
      accs[nf][1] += __ldg(prow0 + i01);
      accs[nf][2] += __ldg(prow1 + i10);
      accs[nf][3] += __ldg(prow1 + i11);
    }

    // ---- online softmax ----
    float mx0 = -1e30f, mx1 = -1e30f;
    #pragma unroll
    for (int nf=0; nf<16; nf++){
      mx0 = fmaxf(mx0, fmaxf(accs[nf][0], accs[nf][1]));
      mx1 = fmaxf(mx1, fmaxf(accs[nf][2], accs[nf][3]));
    }
    mx0 = fmaxf(mx0, __shfl_xor_sync(0xffffffffu, mx0, 1));
    mx0 = fmaxf(mx0, __shfl_xor_sync(0xffffffffu, mx0, 2));
    mx1 = fmaxf(mx1, __shfl_xor_sync(0xffffffffu, mx1, 1));
    mx1 = fmaxf(mx1, __shfl_xor_sync(0xffffffffu, mx1, 2));
    const float mn0 = fmaxf(m0, mx0), mn1 = fmaxf(m1, mx1);
    const float cr0 = __expf(m0 - mn0), cr1 = __expf(m1 - mn1);
    m0 = mn0; m1 = mn1;

    float rs0 = 0.f, rs1 = 0.f;
    uint32_t a_p[8][4];
    #pragma unroll
    for (int kf=0; kf<8; kf++){
      float p00 = __expf(accs[2*kf  ][0] - m0);
      float p01 = __expf(accs[2*kf  ][1] - m0);
      float p10 = __expf(accs[2*kf  ][2] - m1);
      float p11 = __expf(accs[2*kf  ][3] - m1);
      float q00 = __expf(accs[2*kf+1][0] - m0);
      float q01 = __expf(accs[2*kf+1][1] - m0);
      float q10 = __expf(accs[2*kf+1][2] - m1);
      float q11 = __expf(accs[2*kf+1][3] - m1);
      rs0 += p00 + p01 + q00 + q01;
      rs1 += p10 + p11 + q10 + q11;
      __half2 hv;
      hv = __floats2half2_rn(p00, p01); a_p[kf][0] = *reinterpret_cast<uint32_t*>(&hv);
      hv = __floats2half2_rn(p10, p11); a_p[kf][1] = *reinterpret_cast<uint32_t*>(&hv);
      hv = __floats2half2_rn(q00, q01); a_p[kf][2] = *reinterpret_cast<uint32_t*>(&hv);
      hv = __floats2half2_rn(q10, q11); a_p[kf][3] = *reinterpret_cast<uint32_t*>(&hv);
    }
    rs0 += __shfl_xor_sync(0xffffffffu, rs0, 1);
    rs0 += __shfl_xor_sync(0xffffffffu, rs0, 2);
    rs1 += __shfl_xor_sync(0xffffffffu, rs1, 1);
    rs1 += __shfl_xor_sync(0xffffffffu, rs1, 2);
    l0 = l0*cr0 + rs0;
    l1 = l1*cr1 + rs1;
    #pragma unroll
    for (int nf=0; nf<8; nf++){
      acc_o[nf][0] *= cr0; acc_o[nf][1] *= cr0;
      acc_o[nf][2] *= cr1; acc_o[nf][3] *= cr1;
    }

    // ---- O += P V ----
    const uint32_t bv_lm = vbase
        + ((((lane & 7) + ((lane >> 3)&1)*8)*FST) + (((lane >> 4)&1)*8))*2;
    #pragma unroll
    for (int kf=0; kf<8; kf++){
      uint32_t bfr[8][2];
      #pragma unroll
      for (int np=0; np<4; np++){
        uint32_t r0,r1,r2,r3;
        ldsm4t(r0,r1,r2,r3, bv_lm + (kf*16*FST + np*16)*2);
        bfr[np*2+0][0]=r0; bfr[np*2+0][1]=r1;
        bfr[np*2+1][0]=r2; bfr[np*2+1][1]=r3;
      }
      #pragma unroll
      for (int nf=0; nf<8; nf++)
        mma_f16(acc_o[nf], a_p[kf], bfr[nf]);
    }

    if (kt + 2 < 8) load_kv(kt+2, (kt+2) - ((kt+2)/3)*3);
    CP_COMMIT();
    __syncthreads();
  }

  const float inv0 = 1.f/l0, inv1 = 1.f/l1;
  __half* orow0 = O + base + (size_t)qrow0*D_;
  __half* orow1 = orow0 + 8*D_;
  #pragma unroll
  for (int nf=0; nf<8; nf++){
    const int col = nf*8 + 2*lc;
    *(__half2*)(orow0 + col) = __floats2half2_rn(acc_o[nf][0]*inv0, acc_o[nf][1]*inv0);
    *(__half2*)(orow1 + col) = __floats2half2_rn(acc_o[nf][2]*inv1, acc_o[nf][3]*inv1);
  }
}

// ---------------- weight transpose fp32 -> fp16 [N,K] ----------------
__global__ void __launch_bounds__(256) transpose_k_h(const float* __restrict__ W,
                                                     __half* __restrict__ Wt,
                                                     int Kd, int Nd)
{
  __shared__ float t[32][33];
  int n = blockIdx.x*32 + threadIdx.x;
  int k = blockIdx.y*32 + threadIdx.y;
  #pragma unroll
  for (int i=0;i<32;i+=8)
    t[threadIdx.y+i][threadIdx.x] = W[(size_t)(k+i)*Nd + n];
  __syncthreads();
  int n2 = blockIdx.x*32 + threadIdx.y;
  int k2 = blockIdx.y*32 + threadIdx.x;
  #pragma unroll
  for (int i=0;i<32;i+=8)
    Wt[(size_t)(n2+i)*Kd + k2] = __float2half_rn(t[threadIdx.x][threadIdx.y+i]);
}

// ---------------- LayerNorm fp32 in -> fp16 out ----------------
__global__ void __launch_bounds__(256) ln_kernel_h(const float* __restrict__ x,
                                                   const float* __restrict__ g,
                                                   const float* __restrict__ bta,
                                                   __half* __restrict__ y)
{
  int row = blockIdx.x;
  int tid = threadIdx.x;
  const float* xr = x + (size_t)row*D_;
  float4 v = *(const float4*)(xr + tid*4);
  float s  = v.x+v.y+v.z+v.w;
  float ss = v.x*v.x+v.y*v.y+v.z*v.z+v.w*v.w;
  s = warp_sum(s); ss = warp_sum(ss);
  __shared__ float sh[16];
  __shared__ float sh_mu, sh_rs;
  int w = tid>>5, lane = tid&31;
  if (lane==0){ sh[w]=s; sh[8+w]=ss; }
  __syncthreads();
  if (tid==0){
    float S=0.f, SS=0.f;
    #pragma unroll
    for (int i=0;i<8;i++){ S+=sh[i]; SS+=sh[8+i]; }
    float mu  = S*(1.f/(float)D_);
    float var = SS*(1.f/(float)D_) - mu*mu;
    sh_mu = mu; sh_rs = rsqrtf(var + EPSLN);
  }
  __syncthreads();
  float mu = sh_mu, rs = sh_rs;
  float4 gv = *(const float4*)(g   + tid*4);
  float4 bv = *(const float4*)(bta + tid*4);
  __half2 h0 = __floats2half2_rn((v.x-mu)*rs*gv.x + bv.x, (v.y-mu)*rs*gv.y + bv.y);
  __half2 h1 = __floats2half2_rn((v.z-mu)*rs*gv.z + bv.z, (v.w-mu)*rs*gv.w + bv.w);
  uint2 pk; pk.x = *(uint32_t*)&h0; pk.y = *(uint32_t*)&h1;
  *(uint2*)(y + (size_t)row*D_ + tid*4) = pk;
}

// ---------------- rel_embed transpose ----------------
__global__ void rel_transpose(const float* __restrict__ rel, float* __restrict__ relT){
  int i = blockIdx.x*256 + threadIdx.x;
  if (i < NREL*HD_){
    int j = i / HD_, d = i % HD_;
    relT[d*NREL + j] = rel[i];
  }
}

// ---------------- rel projection (reads fp16 Q; output pre-scaled) --------
__global__ void __launch_bounds__(256) rel_proj(const __half* __restrict__ Q,
                                                const float* __restrict__ relT,
                                                float* __restrict__ P)
{
  int bs = blockIdx.x;
  __shared__ float sq[D_];
  int tid = threadIdx.x;
  {
    uint2 raw = *(const uint2*)(Q + (size_t)bs*D_ + tid*4);
    __half2 h0 = *reinterpret_cast<__half2*>(&raw.x);
    __half2 h1 = *reinterpret_cast<__half2*>(&raw.y);
    sq[tid*4+0] = __low2float(h0); sq[tid*4+1] = __high2float(h0);
    sq[tid*4+2] = __low2float(h1); sq[tid*4+3] = __high2float(h1);
  }
  __syncthreads();

  int hg = tid >> 6;
  int jt = tid & 63;
  float acc[4][5];
  #pragma unroll
  for (int a=0;a<4;a++)
    #pragma unroll
    for (int g=0;g<5;g++) acc[a][g]=0.f;

  for (int d=0; d<HD_; d++){
    const float* rrow = relT + d*NREL;
    float rv[5];
    #pragma unroll
    for (int g=0; g<4; g++) rv[g] = __ldg(rrow + jt + 64*g);
    rv[4] = (jt==0) ? __ldg(rrow + 256) : 0.f;
    #pragma unroll
    for (int hh=0; hh<4; hh++){
      float qv = sq[(hg + 4*hh)*HD_ + d];
      #pragma unroll
      for (int g=0; g<5; g++) acc[hh][g] = fmaf(qv, rv[g], acc[hh][g]);
    }
  }
  #pragma unroll
  for (int hh=0; hh<4; hh++){
    int h = hg + 4*hh;
    float* prow = P + ((size_t)bs*H_ + h)*NREL;
    #pragma unroll
    for (int g=0; g<4; g++) prow[jt + 64*g] = acc[hh][g]*0.125f;
    if (jt==0) prow[256] = acc[hh][4]*0.125f;
  }
}

// ---------------- launcher ----------------
#define GEMM_SMEM   (6*HBYTES)           // 61440

extern "C" void kernel_launch(void* const* d_in, const int* in_sizes, int n_in,
                              void* d_out, int out_size)
{
  const float* x    = (const float*)d_in[0];
  const float* wq   = (const float*)d_in[1];
  const float* bq   = (const float*)d_in[2];
  const float* wk   = (const float*)d_in[3];
  const float* bk   = (const float*)d_in[4];
  const float* wv   = (const float*)d_in[5];
  const float* bv   = (const float*)d_in[6];
  const float* wo   = (const float*)d_in[7];
  const float* bo   = (const float*)d_in[8];
  const float* rel  = (const float*)d_in[9];
  const float* ln1g = (const float*)d_in[10];
  const float* ln1b = (const float*)d_in[11];
  const float* ln2g = (const float*)d_in[12];
  const float* ln2b = (const float*)d_in[13];
  const float* w1   = (const float*)d_in[14];
  const float* b1   = (const float*)d_in[15];
  const float* w2   = (const float*)d_in[16];
  const float* b2   = (const float*)d_in[17];
  float* out = (float*)d_out;

  __half *h16_, *q16_, *k16_, *v16_, *o16_, *ff16_;
  __half *wqT_, *wkT_, *wvT_, *woT_, *w1T_, *w2T_;
  float *relT_, *p_, *x2_;
  cudaGetSymbolAddress((void**)&h16_, g_h16);
  cudaGetSymbolAddress((void**)&q16_, g_q16);
  cudaGetSymbolAddress((void**)&k16_, g_k16);
  cudaGetSymbolAddress((void**)&v16_, g_v16);
  cudaGetSymbolAddress((void**)&o16_, g_o16);
  cudaGetSymbolAddress((void**)&ff16_,g_ff16);
  cudaGetSymbolAddress((void**)&relT_,g_relT);
  cudaGetSymbolAddress((void**)&p_,   g_p);
  cudaGetSymbolAddress((void**)&x2_,  g_x2);
  cudaGetSymbolAddress((void**)&wqT_, g_wqT);
  cudaGetSymbolAddress((void**)&wkT_, g_wkT);
  cudaGetSymbolAddress((void**)&wvT_, g_wvT);
  cudaGetSymbolAddress((void**)&woT_, g_woT);
  cudaGetSymbolAddress((void**)&w1T_, g_w1T);
  cudaGetSymbolAddress((void**)&w2T_, g_w2T);

  static bool attr_done = false;
  if (!attr_done){
    cudaFuncSetAttribute(hgemm<EPI_BIAS,1>,       cudaFuncAttributeMaxDynamicSharedMemorySize, GEMM_SMEM);
    cudaFuncSetAttribute(hgemm<EPI_BIAS_RESID,0>, cudaFuncAttributeMaxDynamicSharedMemorySize, GEMM_SMEM);
    cudaFuncSetAttribute(hgemm<EPI_BIAS_GELU,1>,  cudaFuncAttributeMaxDynamicSharedMemorySize, GEMM_SMEM);
    cudaFuncSetAttribute(flash_attn, cudaFuncAttributeMaxDynamicSharedMemorySize, FLASH_SMEM);
    attr_done = true;
  }

  // 0. weight transposes -> fp16 [N,K]
  transpose_k_h<<<dim3(D_/32,   D_/32),  dim3(32,8)>>>(wq, wqT_, D_,   D_);
  transpose_k_h<<<dim3(D_/32,   D_/32),  dim3(32,8)>>>(wk, wkT_, D_,   D_);
  transpose_k_h<<<dim3(D_/32,   D_/32),  dim3(32,8)>>>(wv, wvT_, D_,   D_);
  transpose_k_h<<<dim3(D_/32,   D_/32),  dim3(32,8)>>>(wo, woT_, D_,   D_);
  transpose_k_h<<<dim3(4*D_/32, D_/32),  dim3(32,8)>>>(w1, w1T_, D_,   4*D_);
  transpose_k_h<<<dim3(D_/32,   4*D_/32),dim3(32,8)>>>(w2, w2T_, 4*D_, D_);

  // 1. LN1 -> fp16
  ln_kernel_h<<<BS_, 256>>>(x, ln1g, ln1b, h16_);
  // 2. Q/K/V projections (fp16 out)
  hgemm<EPI_BIAS,1><<<dim3(8,32), 256, GEMM_SMEM>>>(h16_, wqT_, bq, nullptr, q16_, BS_, D_, D_);
  hgemm<EPI_BIAS,1><<<dim3(8,32), 256, GEMM_SMEM>>>(h16_, wkT_, bk, nullptr, k16_, BS_, D_, D_);
  hgemm<EPI_BIAS,1><<<dim3(8,32), 256, GEMM_SMEM>>>(h16_, wvT_, bv, nullptr, v16_, BS_, D_, D_);
  // 3. rel projection (pre-scaled by 1/8)
  rel_transpose<<<(NREL*HD_ + 255)/256, 256>>>(rel, relT_);
  rel_proj<<<BS_, 256>>>(q16_, relT_, p_);
  // 4. fused flash attention -> o16
  flash_attn<<<dim3(8, Bb_*H_), 256, FLASH_SMEM>>>(q16_, k16_, v16_, p_, o16_);
  // 5. output projection + residual (fp32 out)
  hgemm<EPI_BIAS_RESID,0><<<dim3(8,32), 256, GEMM_SMEM>>>(o16_, woT_, bo, x, x2_, BS_, D_, D_);
  // 6. LN2 -> fp16
  ln_kernel_h<<<BS_, 256>>>(x2_, ln2g, ln2b, h16_);
  // 7. FFN1 + exact GELU (fp16 out)
  hgemm<EPI_BIAS_GELU,1><<<dim3(32,32), 256, GEMM_SMEM>>>(h16_, w1T_, b1, nullptr, ff16_, BS_, 4*D_, D_);
  // 8. FFN2 + residual -> out (fp32)
  hgemm<EPI_BIAS_RESID,0><<<dim3(8,32), 256, GEMM_SMEM>>>(ff16_, w2T_, b2, x2_, out, BS_, D_, 4*D_);
}